// round 1
// baseline (speedup 1.0000x reference)
#include <cuda_runtime.h>
#include <math.h>

#define BATCH   8
#define SEQ     512
#define DIM     512
#define NHEADS  8
#define DHEAD   64
#define MEMN    4096
#define TOPK    32
#define FFDIM   2048
#define DEPTH   6
#define MROWS   (BATCH*SEQ)   /* 4096 */
#define ATT_SCALE 0.125f      /* DH^-0.5 */

// ---------------- scratch (device globals; no allocation allowed) ----------
__device__ float g_X [MROWS*DIM];
__device__ float g_H [MROWS*DIM];
__device__ float g_Q [MROWS*DIM];
__device__ float g_K [MROWS*DIM];
__device__ float g_V [MROWS*DIM];
__device__ float g_AO[MROWS*DIM];
__device__ float g_FF[MROWS*FFDIM];

__device__ __forceinline__ float warp_sum(float v) {
    #pragma unroll
    for (int o = 16; o > 0; o >>= 1) v += __shfl_xor_sync(0xffffffffu, v, o);
    return v;
}

// ---------------- LayerNorm: one row (512) per block, 128 threads ----------
__global__ void ln_kernel(const float* __restrict__ x,
                          const float* __restrict__ sc,
                          const float* __restrict__ bi,
                          float* __restrict__ out) {
    int row = blockIdx.x;
    int tid = threadIdx.x;
    const float4* xr = reinterpret_cast<const float4*>(x + (size_t)row * DIM);
    float4 v = xr[tid];
    float s  = v.x + v.y + v.z + v.w;
    float sq = v.x*v.x + v.y*v.y + v.z*v.z + v.w*v.w;
    __shared__ float ss[4], sqs[4];
    s  = warp_sum(s);
    sq = warp_sum(sq);
    int w = tid >> 5, lane = tid & 31;
    if (lane == 0) { ss[w] = s; sqs[w] = sq; }
    __syncthreads();
    float tot  = ss[0] + ss[1] + ss[2] + ss[3];
    float totq = sqs[0] + sqs[1] + sqs[2] + sqs[3];
    float mean = tot * (1.0f / DIM);
    float var  = totq * (1.0f / DIM) - mean * mean;
    float rstd = rsqrtf(var + 1e-5f);
    float4 sv = reinterpret_cast<const float4*>(sc)[tid];
    float4 bv = reinterpret_cast<const float4*>(bi)[tid];
    float4 o;
    o.x = (v.x - mean) * rstd * sv.x + bv.x;
    o.y = (v.y - mean) * rstd * sv.y + bv.y;
    o.z = (v.z - mean) * rstd * sv.z + bv.z;
    o.w = (v.w - mean) * rstd * sv.w + bv.w;
    reinterpret_cast<float4*>(out + (size_t)row * DIM)[tid] = o;
}

// ---------------- SGEMM: C = A(MxK) @ B(KxN) (+R), 128x128x8 tile ----------
__global__ __launch_bounds__(256)
void sgemm(const float* __restrict__ A, const float* __restrict__ B,
           const float* __restrict__ R, float* __restrict__ C,
           int M, int N, int K) {
    __shared__ float As[8][128];
    __shared__ float Bs[8][128];
    int bx = blockIdx.x, by = blockIdx.y;
    int tid = threadIdx.x;
    int tx = tid & 15, ty = tid >> 4;
    int aRow = tid >> 1;            // 128 rows
    int aCol = (tid & 1) * 4;       // 2 threads x float4 per row
    int bRow = tid >> 5;            // 8 rows
    int bCol = (tid & 31) * 4;      // 32 threads x float4 per row
    const float* Ab = A + (size_t)by * 128 * K;
    const float* Bb = B + (size_t)bx * 128;
    float acc[8][8];
    #pragma unroll
    for (int i = 0; i < 8; i++)
        #pragma unroll
        for (int j = 0; j < 8; j++) acc[i][j] = 0.f;

    for (int k0 = 0; k0 < K; k0 += 8) {
        float4 a4 = *reinterpret_cast<const float4*>(Ab + (size_t)aRow * K + k0 + aCol);
        As[aCol+0][aRow] = a4.x; As[aCol+1][aRow] = a4.y;
        As[aCol+2][aRow] = a4.z; As[aCol+3][aRow] = a4.w;
        float4 b4 = *reinterpret_cast<const float4*>(Bb + (size_t)(k0 + bRow) * N + bCol);
        *reinterpret_cast<float4*>(&Bs[bRow][bCol]) = b4;
        __syncthreads();
        #pragma unroll
        for (int k = 0; k < 8; k++) {
            float ar[8], br[8];
            #pragma unroll
            for (int i = 0; i < 8; i++) ar[i] = As[k][ty*8 + i];
            #pragma unroll
            for (int j = 0; j < 8; j++) br[j] = Bs[k][tx*8 + j];
            #pragma unroll
            for (int i = 0; i < 8; i++)
                #pragma unroll
                for (int j = 0; j < 8; j++) acc[i][j] += ar[i] * br[j];
        }
        __syncthreads();
    }
    #pragma unroll
    for (int i = 0; i < 8; i++) {
        size_t row = (size_t)by * 128 + ty*8 + i;
        #pragma unroll
        for (int j = 0; j < 8; j += 4) {
            size_t col = (size_t)bx * 128 + tx*8 + j;
            float4 o = make_float4(acc[i][j], acc[i][j+1], acc[i][j+2], acc[i][j+3]);
            if (R) {
                float4 r = *reinterpret_cast<const float4*>(R + row * N + col);
                o.x += r.x; o.y += r.y; o.z += r.z; o.w += r.w;
            }
            *reinterpret_cast<float4*>(C + row * N + col) = o;
        }
    }
}

// ---------------- GELU (tanh approximation, matches jax.nn.gelu) -----------
__global__ void gelu_kernel(float* __restrict__ x, int n) {
    int i = blockIdx.x * blockDim.x + threadIdx.x;
    int stride = gridDim.x * blockDim.x;
    for (; i < n; i += stride) {
        float v = x[i];
        float c = v + 0.044715f * v * v * v;
        x[i] = 0.5f * v * (1.0f + tanhf(0.7978845608028654f * c));
    }
}

// ---------------- local causal attention: one (b,h,i) per block ------------
__global__ __launch_bounds__(128)
void attn_local(const float* __restrict__ Q, const float* __restrict__ Kp,
                const float* __restrict__ V, float* __restrict__ O) {
    int i = blockIdx.x, h = blockIdx.y, b = blockIdx.z;
    int tid = threadIdx.x, lane = tid & 31, w = tid >> 5;
    __shared__ float qs[DHEAD];
    __shared__ float p[SEQ];
    __shared__ float red[128];

    if (tid < DHEAD) qs[tid] = Q[((size_t)(b*SEQ + i)) * DIM + h*DHEAD + tid];
    __syncthreads();

    // sims for j<=i, 4 warps
    for (int j = w; j <= i; j += 4) {
        const float* kr = Kp + ((size_t)(b*SEQ + j)) * DIM + h*DHEAD;
        float part = qs[lane] * kr[lane] + qs[lane+32] * kr[lane+32];
        part = warp_sum(part);
        if (lane == 0) p[j] = part * ATT_SCALE;
    }
    __syncthreads();

    // softmax over [0,i]
    float lm = -1e30f;
    for (int j = tid; j <= i; j += 128) lm = fmaxf(lm, p[j]);
    red[tid] = lm; __syncthreads();
    for (int s = 64; s > 0; s >>= 1) { if (tid < s) red[tid] = fmaxf(red[tid], red[tid+s]); __syncthreads(); }
    float mx = red[0]; __syncthreads();
    float ls = 0.f;
    for (int j = tid; j <= i; j += 128) { float e = __expf(p[j] - mx); p[j] = e; ls += e; }
    red[tid] = ls; __syncthreads();
    for (int s = 64; s > 0; s >>= 1) { if (tid < s) red[tid] += red[tid+s]; __syncthreads(); }
    float inv = 1.0f / red[0]; __syncthreads();

    // AV: 2 partials per d
    int part2 = tid >> 6, d = tid & 63;
    float acc = 0.f;
    for (int j = part2; j <= i; j += 2)
        acc += p[j] * V[((size_t)(b*SEQ + j)) * DIM + h*DHEAD + d];
    red[tid] = acc; __syncthreads();
    if (part2 == 0)
        O[((size_t)(b*SEQ + i)) * DIM + h*DHEAD + d] = (red[tid] + red[tid+64]) * inv;
}

// ---------------- KNN-memory attention: one (b,h,i) per block --------------
__global__ __launch_bounds__(256)
void attn_knn(const float* __restrict__ Q, const float* __restrict__ Kp,
              const float* __restrict__ V, const float* __restrict__ MK,
              const float* __restrict__ MV, float* __restrict__ O) {
    int i = blockIdx.x, h = blockIdx.y, b = blockIdx.z;
    int tid = threadIdx.x, lane = tid & 31, w = tid >> 5;
    __shared__ float qs[DHEAD];
    __shared__ float sm[MEMN];       // 16 KB
    __shared__ float p[SEQ];
    __shared__ float tval[TOPK];
    __shared__ int   tindex[TOPK];
    __shared__ float red[256];
    __shared__ int   redi[256];

    if (tid < DHEAD) qs[tid] = Q[((size_t)(b*SEQ + i)) * DIM + h*DHEAD + tid];
    __syncthreads();

    // memory sims: 8 warps over 4096 rows
    const float* mkb = MK + (size_t)b * MEMN * DHEAD;
    for (int m = w; m < MEMN; m += 8) {
        const float* mr = mkb + (size_t)m * DHEAD;
        float part = qs[lane] * mr[lane] + qs[lane+32] * mr[lane+32];
        part = warp_sum(part);
        if (lane == 0) sm[m] = part * ATT_SCALE;
    }
    __syncthreads();

    // iterative argmax top-32 (order irrelevant: output is sum over picks)
    for (int t = 0; t < TOPK; t++) {
        float best = -1e30f; int bi2 = 0;
        for (int m = tid; m < MEMN; m += 256) {
            float v = sm[m];
            if (v > best) { best = v; bi2 = m; }
        }
        red[tid] = best; redi[tid] = bi2; __syncthreads();
        for (int s = 128; s > 0; s >>= 1) {
            if (tid < s && red[tid+s] > red[tid]) { red[tid] = red[tid+s]; redi[tid] = redi[tid+s]; }
            __syncthreads();
        }
        if (tid == 0) { tval[t] = red[0]; tindex[t] = redi[0]; sm[redi[0]] = -1e30f; }
        __syncthreads();
    }

    // local sims for j<=i, 8 warps
    for (int j = w; j <= i; j += 8) {
        const float* kr = Kp + ((size_t)(b*SEQ + j)) * DIM + h*DHEAD;
        float part = qs[lane] * kr[lane] + qs[lane+32] * kr[lane+32];
        part = warp_sum(part);
        if (lane == 0) p[j] = part * ATT_SCALE;
    }
    __syncthreads();

    // softmax over top-32 + local [0,i]
    float lm = -1e30f;
    for (int j = tid; j <= i; j += 256) lm = fmaxf(lm, p[j]);
    if (tid < TOPK) lm = fmaxf(lm, tval[tid]);
    red[tid] = lm; __syncthreads();
    for (int s = 128; s > 0; s >>= 1) { if (tid < s) red[tid] = fmaxf(red[tid], red[tid+s]); __syncthreads(); }
    float mx = red[0]; __syncthreads();
    float ls = 0.f;
    for (int j = tid; j <= i; j += 256) { float e = __expf(p[j] - mx); p[j] = e; ls += e; }
    if (tid < TOPK) { float e = __expf(tval[tid] - mx); tval[tid] = e; ls += e; }
    red[tid] = ls; __syncthreads();
    for (int s = 128; s > 0; s >>= 1) { if (tid < s) red[tid] += red[tid+s]; __syncthreads(); }
    float inv = 1.0f / red[0]; __syncthreads();

    // output: 4 partials per d; part 0 also handles memory terms
    int part4 = tid >> 6, d = tid & 63;
    float acc = 0.f;
    if (part4 == 0) {
        const float* mvb = MV + (size_t)b * MEMN * DHEAD;
        #pragma unroll
        for (int t = 0; t < TOPK; t++)
            acc += tval[t] * mvb[(size_t)tindex[t] * DHEAD + d];
    }
    for (int j = part4; j <= i; j += 4)
        acc += p[j] * V[((size_t)(b*SEQ + j)) * DIM + h*DHEAD + d];
    red[tid] = acc; __syncthreads();
    if (part4 == 0)
        O[((size_t)(b*SEQ + i)) * DIM + h*DHEAD + d] =
            (red[tid] + red[tid+64] + red[tid+128] + red[tid+192]) * inv;
}

// ---------------- host orchestration --------------------------------------
extern "C" void kernel_launch(void* const* d_in, const int* in_sizes, int n_in,
                              void* d_out, int out_size) {
    const float* x     = (const float*)d_in[0];
    const float* Wq    = (const float*)d_in[1];
    const float* Wk    = (const float*)d_in[2];
    const float* Wv    = (const float*)d_in[3];
    const float* Wo    = (const float*)d_in[4];
    const float* ln1s  = (const float*)d_in[5];
    const float* ln1b  = (const float*)d_in[6];
    const float* ln2s  = (const float*)d_in[7];
    const float* ln2b  = (const float*)d_in[8];
    const float* W1    = (const float*)d_in[9];
    const float* W2    = (const float*)d_in[10];
    const float* lnfs  = (const float*)d_in[11];
    const float* lnfb  = (const float*)d_in[12];
    const float* mem_k = (const float*)d_in[13];
    const float* mem_v = (const float*)d_in[14];

    float *X, *H, *Q, *K, *V, *AO, *FFb;
    cudaGetSymbolAddress((void**)&X,  g_X);
    cudaGetSymbolAddress((void**)&H,  g_H);
    cudaGetSymbolAddress((void**)&Q,  g_Q);
    cudaGetSymbolAddress((void**)&K,  g_K);
    cudaGetSymbolAddress((void**)&V,  g_V);
    cudaGetSymbolAddress((void**)&AO, g_AO);
    cudaGetSymbolAddress((void**)&FFb, g_FF);

    cudaMemcpyAsync(X, x, sizeof(float) * MROWS * DIM, cudaMemcpyDeviceToDevice);

    dim3 gD(DIM/128, MROWS/128);     // 4 x 32
    dim3 gF(FFDIM/128, MROWS/128);   // 16 x 32
    dim3 gAtt(SEQ, NHEADS, BATCH);

    int mi = 0;
    for (int l = 0; l < DEPTH; l++) {
        ln_kernel<<<MROWS, 128>>>(X, ln1s + l*DIM, ln1b + l*DIM, H);
        sgemm<<<gD, 256>>>(H, Wq + (size_t)l*DIM*DIM, nullptr, Q, MROWS, DIM, DIM);
        sgemm<<<gD, 256>>>(H, Wk + (size_t)l*DIM*DIM, nullptr, K, MROWS, DIM, DIM);
        sgemm<<<gD, 256>>>(H, Wv + (size_t)l*DIM*DIM, nullptr, V, MROWS, DIM, DIM);
        if (l == 3 || l == 4) {
            attn_knn<<<gAtt, 256>>>(Q, K, V,
                                    mem_k + (size_t)mi * BATCH * MEMN * DHEAD,
                                    mem_v + (size_t)mi * BATCH * MEMN * DHEAD, AO);
            mi++;
        } else {
            attn_local<<<gAtt, 128>>>(Q, K, V, AO);
        }
        sgemm<<<gD, 256>>>(AO, Wo + (size_t)l*DIM*DIM, X, X, MROWS, DIM, DIM);
        ln_kernel<<<MROWS, 128>>>(X, ln2s + l*DIM, ln2b + l*DIM, H);
        sgemm<<<gF, 256>>>(H, W1 + (size_t)l*DIM*FFDIM, nullptr, FFb, MROWS, FFDIM, DIM);
        gelu_kernel<<<4096, 256>>>(FFb, MROWS * FFDIM);
        sgemm<<<gD, 256>>>(FFb, W2 + (size_t)l*FFDIM*DIM, X, X, MROWS, DIM, FFDIM);
    }
    ln_kernel<<<MROWS, 128>>>(X, lnfs, lnfb, (float*)d_out);
}

// round 2
// speedup vs baseline: 1.6976x; 1.6976x over previous
#include <cuda_runtime.h>
#include <math.h>

#define BATCH   8
#define SEQ     512
#define DIM     512
#define NHEADS  8
#define DHEAD   64
#define MEMN    4096
#define TOPK    32
#define FFDIM   2048
#define DEPTH   6
#define MROWS   (BATCH*SEQ)   /* 4096 */
#define NBH     (BATCH*NHEADS) /* 64 */
#define ATT_SCALE 0.125f      /* DH^-0.5 */

// ---------------- scratch (device globals; no allocation allowed) ----------
__device__ float g_X [MROWS*DIM];
__device__ float g_H [MROWS*DIM];
__device__ float g_Q [MROWS*DIM];
__device__ float g_K [MROWS*DIM];
__device__ float g_V [MROWS*DIM];
__device__ float g_AO[MROWS*DIM];
__device__ float g_FF[MROWS*FFDIM];
__device__ float g_S [(size_t)NBH*SEQ*MEMN];   // 512 MB sims buffer
__device__ float g_TV[(size_t)NBH*SEQ*TOPK];
__device__ int   g_TI[(size_t)NBH*SEQ*TOPK];

__device__ __forceinline__ float warp_sum(float v) {
    #pragma unroll
    for (int o = 16; o > 0; o >>= 1) v += __shfl_xor_sync(0xffffffffu, v, o);
    return v;
}

__device__ __forceinline__ float gelu_f(float v) {
    float c = v + 0.044715f * v * v * v;
    return 0.5f * v * (1.0f + tanhf(0.7978845608028654f * c));
}

// ---------------- LayerNorm: one row (512) per block, 128 threads ----------
__global__ void ln_kernel(const float* __restrict__ x,
                          const float* __restrict__ sc,
                          const float* __restrict__ bi,
                          float* __restrict__ out) {
    int row = blockIdx.x;
    int tid = threadIdx.x;
    const float4* xr = reinterpret_cast<const float4*>(x + (size_t)row * DIM);
    float4 v = xr[tid];
    float s  = v.x + v.y + v.z + v.w;
    float sq = v.x*v.x + v.y*v.y + v.z*v.z + v.w*v.w;
    __shared__ float ss[4], sqs[4];
    s  = warp_sum(s);
    sq = warp_sum(sq);
    int w = tid >> 5, lane = tid & 31;
    if (lane == 0) { ss[w] = s; sqs[w] = sq; }
    __syncthreads();
    float tot  = ss[0] + ss[1] + ss[2] + ss[3];
    float totq = sqs[0] + sqs[1] + sqs[2] + sqs[3];
    float mean = tot * (1.0f / DIM);
    float var  = totq * (1.0f / DIM) - mean * mean;
    float rstd = rsqrtf(var + 1e-5f);
    float4 sv = reinterpret_cast<const float4*>(sc)[tid];
    float4 bv = reinterpret_cast<const float4*>(bi)[tid];
    float4 o;
    o.x = (v.x - mean) * rstd * sv.x + bv.x;
    o.y = (v.y - mean) * rstd * sv.y + bv.y;
    o.z = (v.z - mean) * rstd * sv.z + bv.z;
    o.w = (v.w - mean) * rstd * sv.w + bv.w;
    reinterpret_cast<float4*>(out + (size_t)row * DIM)[tid] = o;
}

// ---------------- SGEMM: C = act(A(MxK) @ B(KxN) (+R)), 128x128x8 tile -----
__global__ __launch_bounds__(256)
void sgemm(const float* __restrict__ A, const float* __restrict__ B,
           const float* __restrict__ R, float* __restrict__ C,
           int M, int N, int K, int act) {
    __shared__ float As[8][128];
    __shared__ float Bs[8][128];
    int bx = blockIdx.x, by = blockIdx.y;
    int tid = threadIdx.x;
    int tx = tid & 15, ty = tid >> 4;
    int aRow = tid >> 1;
    int aCol = (tid & 1) * 4;
    int bRow = tid >> 5;
    int bCol = (tid & 31) * 4;
    const float* Ab = A + (size_t)by * 128 * K;
    const float* Bb = B + (size_t)bx * 128;
    float acc[8][8];
    #pragma unroll
    for (int i = 0; i < 8; i++)
        #pragma unroll
        for (int j = 0; j < 8; j++) acc[i][j] = 0.f;

    for (int k0 = 0; k0 < K; k0 += 8) {
        float4 a4 = *reinterpret_cast<const float4*>(Ab + (size_t)aRow * K + k0 + aCol);
        As[aCol+0][aRow] = a4.x; As[aCol+1][aRow] = a4.y;
        As[aCol+2][aRow] = a4.z; As[aCol+3][aRow] = a4.w;
        float4 b4 = *reinterpret_cast<const float4*>(Bb + (size_t)(k0 + bRow) * N + bCol);
        *reinterpret_cast<float4*>(&Bs[bRow][bCol]) = b4;
        __syncthreads();
        #pragma unroll
        for (int k = 0; k < 8; k++) {
            float ar[8], br[8];
            #pragma unroll
            for (int i = 0; i < 8; i++) ar[i] = As[k][ty*8 + i];
            #pragma unroll
            for (int j = 0; j < 8; j++) br[j] = Bs[k][tx*8 + j];
            #pragma unroll
            for (int i = 0; i < 8; i++)
                #pragma unroll
                for (int j = 0; j < 8; j++) acc[i][j] += ar[i] * br[j];
        }
        __syncthreads();
    }
    #pragma unroll
    for (int i = 0; i < 8; i++) {
        size_t row = (size_t)by * 128 + ty*8 + i;
        #pragma unroll
        for (int j = 0; j < 8; j += 4) {
            size_t col = (size_t)bx * 128 + tx*8 + j;
            float4 o = make_float4(acc[i][j], acc[i][j+1], acc[i][j+2], acc[i][j+3]);
            if (act) {
                o.x = gelu_f(o.x); o.y = gelu_f(o.y);
                o.z = gelu_f(o.z); o.w = gelu_f(o.w);
            }
            if (R) {
                float4 r = *reinterpret_cast<const float4*>(R + row * N + col);
                o.x += r.x; o.y += r.y; o.z += r.z; o.w += r.w;
            }
            *reinterpret_cast<float4*>(C + row * N + col) = o;
        }
    }
}

// -------- KNN sim GEMM (NT): S[bh,i,m] = scale * sum_d Q[b,i,h,d]*MK[b,m,d]
__global__ __launch_bounds__(256)
void knn_sim(const float* __restrict__ Q, const float* __restrict__ MK,
             float* __restrict__ S) {
    __shared__ float As[8][128];   // [d][i]
    __shared__ float Bs[8][128];   // [d][m]
    int bh = blockIdx.z;
    int b = bh >> 3, h = bh & 7;
    int tid = threadIdx.x;
    int tx = tid & 15, ty = tid >> 4;
    int lRow = tid >> 1;
    int lCol = (tid & 1) * 4;

    const float* Qb = Q + ((size_t)(b*SEQ + blockIdx.y*128 + lRow)) * DIM + h*DHEAD + lCol;
    const float* Mb = MK + ((size_t)(b*MEMN + blockIdx.x*128 + lRow)) * DHEAD + lCol;

    float acc[8][8];
    #pragma unroll
    for (int i = 0; i < 8; i++)
        #pragma unroll
        for (int j = 0; j < 8; j++) acc[i][j] = 0.f;

    for (int k0 = 0; k0 < DHEAD; k0 += 8) {
        float4 a4 = *reinterpret_cast<const float4*>(Qb + k0);
        As[lCol+0][lRow] = a4.x; As[lCol+1][lRow] = a4.y;
        As[lCol+2][lRow] = a4.z; As[lCol+3][lRow] = a4.w;
        float4 b4 = *reinterpret_cast<const float4*>(Mb + k0);
        Bs[lCol+0][lRow] = b4.x; Bs[lCol+1][lRow] = b4.y;
        Bs[lCol+2][lRow] = b4.z; Bs[lCol+3][lRow] = b4.w;
        __syncthreads();
        #pragma unroll
        for (int k = 0; k < 8; k++) {
            float ar[8], br[8];
            #pragma unroll
            for (int i = 0; i < 8; i++) ar[i] = As[k][ty*8 + i];
            #pragma unroll
            for (int j = 0; j < 8; j++) br[j] = Bs[k][tx*8 + j];
            #pragma unroll
            for (int i = 0; i < 8; i++)
                #pragma unroll
                for (int j = 0; j < 8; j++) acc[i][j] += ar[i] * br[j];
        }
        __syncthreads();
    }
    #pragma unroll
    for (int i = 0; i < 8; i++) {
        size_t iG = (size_t)blockIdx.y * 128 + ty*8 + i;
        #pragma unroll
        for (int j = 0; j < 8; j += 4) {
            size_t mG = (size_t)blockIdx.x * 128 + tx*8 + j;
            float4 o = make_float4(acc[i][j]*ATT_SCALE, acc[i][j+1]*ATT_SCALE,
                                   acc[i][j+2]*ATT_SCALE, acc[i][j+3]*ATT_SCALE);
            *reinterpret_cast<float4*>(S + ((size_t)bh*SEQ + iG)*MEMN + mG) = o;
        }
    }
}

// -------- top-32 per (bh,i): iterative argmax, 2 barriers/iter -------------
__global__ __launch_bounds__(256)
void topk_kernel(const float* __restrict__ S, float* __restrict__ TV,
                 int* __restrict__ TI) {
    int i = blockIdx.x, bh = blockIdx.y;
    const float* row = S + ((size_t)bh*SEQ + i)*MEMN;
    __shared__ float sv[MEMN];
    __shared__ float wv[8];
    __shared__ int   wi[8];
    __shared__ float winv; __shared__ int wini;
    int tid = threadIdx.x;

    float lmax = -1e30f; int lidx = 0;
    #pragma unroll 4
    for (int j = 0; j < 16; j++) {
        int m = tid + 256*j;
        float v = row[m];
        sv[m] = v;
        if (v > lmax) { lmax = v; lidx = m; }
    }
    // sv slots touched only by their owner thread: no barrier needed for init.
    for (int t = 0; t < TOPK; t++) {
        float v = lmax; int idx = lidx;
        #pragma unroll
        for (int o = 16; o > 0; o >>= 1) {
            float ov = __shfl_xor_sync(0xffffffffu, v, o);
            int   oi = __shfl_xor_sync(0xffffffffu, idx, o);
            if (ov > v) { v = ov; idx = oi; }
        }
        if ((tid & 31) == 0) { wv[tid>>5] = v; wi[tid>>5] = idx; }
        __syncthreads();
        if (tid < 32) {
            float v2 = (tid < 8) ? wv[tid] : -1e30f;
            int   i2 = (tid < 8) ? wi[tid] : 0;
            #pragma unroll
            for (int o = 4; o > 0; o >>= 1) {
                float ov = __shfl_xor_sync(0xffffffffu, v2, o);
                int   oi = __shfl_xor_sync(0xffffffffu, i2, o);
                if (ov > v2) { v2 = ov; i2 = oi; }
            }
            if (tid == 0) {
                winv = v2; wini = i2;
                TV[((size_t)bh*SEQ + i)*TOPK + t] = v2;
                TI[((size_t)bh*SEQ + i)*TOPK + t] = i2;
            }
        }
        __syncthreads();
        int widx = wini;
        if ((widx & 255) == tid) {
            sv[widx] = -1e30f;
            lmax = -1e30f; lidx = 0;
            #pragma unroll 4
            for (int j = 0; j < 16; j++) {
                int m = tid + 256*j;
                float vv = sv[m];
                if (vv > lmax) { lmax = vv; lidx = m; }
            }
        }
    }
}

// ---------------- local causal attention: one (b,h,i) per block ------------
__global__ __launch_bounds__(128)
void attn_local(const float* __restrict__ Q, const float* __restrict__ Kp,
                const float* __restrict__ V, float* __restrict__ O) {
    int i = blockIdx.x, h = blockIdx.y, b = blockIdx.z;
    int tid = threadIdx.x, lane = tid & 31, w = tid >> 5;
    __shared__ float qs[DHEAD];
    __shared__ float p[SEQ];
    __shared__ float red[128];

    if (tid < DHEAD) qs[tid] = Q[((size_t)(b*SEQ + i)) * DIM + h*DHEAD + tid];
    __syncthreads();

    for (int j = w; j <= i; j += 4) {
        const float* kr = Kp + ((size_t)(b*SEQ + j)) * DIM + h*DHEAD;
        float part = qs[lane] * kr[lane] + qs[lane+32] * kr[lane+32];
        part = warp_sum(part);
        if (lane == 0) p[j] = part * ATT_SCALE;
    }
    __syncthreads();

    float lm = -1e30f;
    for (int j = tid; j <= i; j += 128) lm = fmaxf(lm, p[j]);
    red[tid] = lm; __syncthreads();
    for (int s = 64; s > 0; s >>= 1) { if (tid < s) red[tid] = fmaxf(red[tid], red[tid+s]); __syncthreads(); }
    float mx = red[0]; __syncthreads();
    float ls = 0.f;
    for (int j = tid; j <= i; j += 128) { float e = __expf(p[j] - mx); p[j] = e; ls += e; }
    red[tid] = ls; __syncthreads();
    for (int s = 64; s > 0; s >>= 1) { if (tid < s) red[tid] += red[tid+s]; __syncthreads(); }
    float inv = 1.0f / red[0]; __syncthreads();

    int part2 = tid >> 6, d = tid & 63;
    float acc = 0.f;
    for (int j = part2; j <= i; j += 2)
        acc += p[j] * V[((size_t)(b*SEQ + j)) * DIM + h*DHEAD + d];
    red[tid] = acc; __syncthreads();
    if (part2 == 0)
        O[((size_t)(b*SEQ + i)) * DIM + h*DHEAD + d] = (red[tid] + red[tid+64]) * inv;
}

// -------- KNN attention using precomputed top-32 ---------------------------
__global__ __launch_bounds__(128)
void attn_knn2(const float* __restrict__ Q, const float* __restrict__ Kp,
               const float* __restrict__ V, const float* __restrict__ MV,
               const float* __restrict__ TV, const int* __restrict__ TI,
               float* __restrict__ O) {
    int i = blockIdx.x, h = blockIdx.y, b = blockIdx.z;
    int bh = b*NHEADS + h;
    int tid = threadIdx.x, lane = tid & 31, w = tid >> 5;
    __shared__ float qs[DHEAD];
    __shared__ float p[SEQ];
    __shared__ float tv[TOPK];
    __shared__ int   ti[TOPK];
    __shared__ float red[128];

    if (tid < DHEAD) qs[tid] = Q[((size_t)(b*SEQ + i)) * DIM + h*DHEAD + tid];
    if (tid >= 64 && tid < 64 + TOPK) {
        int t = tid - 64;
        tv[t] = TV[((size_t)bh*SEQ + i)*TOPK + t];
        ti[t] = TI[((size_t)bh*SEQ + i)*TOPK + t];
    }
    __syncthreads();

    for (int j = w; j <= i; j += 4) {
        const float* kr = Kp + ((size_t)(b*SEQ + j)) * DIM + h*DHEAD;
        float part = qs[lane] * kr[lane] + qs[lane+32] * kr[lane+32];
        part = warp_sum(part);
        if (lane == 0) p[j] = part * ATT_SCALE;
    }
    __syncthreads();

    float lm = -1e30f;
    for (int j = tid; j <= i; j += 128) lm = fmaxf(lm, p[j]);
    if (tid < TOPK) lm = fmaxf(lm, tv[tid]);
    red[tid] = lm; __syncthreads();
    for (int s = 64; s > 0; s >>= 1) { if (tid < s) red[tid] = fmaxf(red[tid], red[tid+s]); __syncthreads(); }
    float mx = red[0]; __syncthreads();
    float ls = 0.f;
    for (int j = tid; j <= i; j += 128) { float e = __expf(p[j] - mx); p[j] = e; ls += e; }
    if (tid < TOPK) { float e = __expf(tv[tid] - mx); tv[tid] = e; ls += e; }
    red[tid] = ls; __syncthreads();
    for (int s = 64; s > 0; s >>= 1) { if (tid < s) red[tid] += red[tid+s]; __syncthreads(); }
    float inv = 1.0f / red[0]; __syncthreads();

    int part2 = tid >> 6, d = tid & 63;
    float acc = 0.f;
    if (part2 == 0) {
        const float* mvb = MV + (size_t)b * MEMN * DHEAD;
        #pragma unroll
        for (int t = 0; t < TOPK; t++)
            acc += tv[t] * mvb[(size_t)ti[t] * DHEAD + d];
    }
    for (int j = part2; j <= i; j += 2)
        acc += p[j] * V[((size_t)(b*SEQ + j)) * DIM + h*DHEAD + d];
    red[tid] = acc; __syncthreads();
    if (part2 == 0)
        O[((size_t)(b*SEQ + i)) * DIM + h*DHEAD + d] = (red[tid] + red[tid+64]) * inv;
}

// ---------------- host orchestration --------------------------------------
extern "C" void kernel_launch(void* const* d_in, const int* in_sizes, int n_in,
                              void* d_out, int out_size) {
    const float* x     = (const float*)d_in[0];
    const float* Wq    = (const float*)d_in[1];
    const float* Wk    = (const float*)d_in[2];
    const float* Wv    = (const float*)d_in[3];
    const float* Wo    = (const float*)d_in[4];
    const float* ln1s  = (const float*)d_in[5];
    const float* ln1b  = (const float*)d_in[6];
    const float* ln2s  = (const float*)d_in[7];
    const float* ln2b  = (const float*)d_in[8];
    const float* W1    = (const float*)d_in[9];
    const float* W2    = (const float*)d_in[10];
    const float* lnfs  = (const float*)d_in[11];
    const float* lnfb  = (const float*)d_in[12];
    const float* mem_k = (const float*)d_in[13];
    const float* mem_v = (const float*)d_in[14];

    float *X, *H, *Q, *K, *V, *AO, *FFb, *S, *TV;
    int *TI;
    cudaGetSymbolAddress((void**)&X,  g_X);
    cudaGetSymbolAddress((void**)&H,  g_H);
    cudaGetSymbolAddress((void**)&Q,  g_Q);
    cudaGetSymbolAddress((void**)&K,  g_K);
    cudaGetSymbolAddress((void**)&V,  g_V);
    cudaGetSymbolAddress((void**)&AO, g_AO);
    cudaGetSymbolAddress((void**)&FFb, g_FF);
    cudaGetSymbolAddress((void**)&S,  g_S);
    cudaGetSymbolAddress((void**)&TV, g_TV);
    cudaGetSymbolAddress((void**)&TI, g_TI);

    cudaMemcpyAsync(X, x, sizeof(float) * MROWS * DIM, cudaMemcpyDeviceToDevice);

    dim3 gD(DIM/128, MROWS/128);
    dim3 gF(FFDIM/128, MROWS/128);
    dim3 gAtt(SEQ, NHEADS, BATCH);
    dim3 gSim(MEMN/128, SEQ/128, NBH);
    dim3 gTop(SEQ, NBH);

    int mi = 0;
    for (int l = 0; l < DEPTH; l++) {
        ln_kernel<<<MROWS, 128>>>(X, ln1s + l*DIM, ln1b + l*DIM, H);
        sgemm<<<gD, 256>>>(H, Wq + (size_t)l*DIM*DIM, nullptr, Q, MROWS, DIM, DIM, 0);
        sgemm<<<gD, 256>>>(H, Wk + (size_t)l*DIM*DIM, nullptr, K, MROWS, DIM, DIM, 0);
        sgemm<<<gD, 256>>>(H, Wv + (size_t)l*DIM*DIM, nullptr, V, MROWS, DIM, DIM, 0);
        if (l == 3 || l == 4) {
            const float* MK = mem_k + (size_t)mi * BATCH * MEMN * DHEAD;
            const float* MV = mem_v + (size_t)mi * BATCH * MEMN * DHEAD;
            knn_sim<<<gSim, 256>>>(Q, MK, S);
            topk_kernel<<<gTop, 256>>>(S, TV, TI);
            attn_knn2<<<gAtt, 128>>>(Q, K, V, MV, TV, TI, AO);
            mi++;
        } else {
            attn_local<<<gAtt, 128>>>(Q, K, V, AO);
        }
        sgemm<<<gD, 256>>>(AO, Wo + (size_t)l*DIM*DIM, X, X, MROWS, DIM, DIM, 0);
        ln_kernel<<<MROWS, 128>>>(X, ln2s + l*DIM, ln2b + l*DIM, H);
        sgemm<<<gF, 256>>>(H, W1 + (size_t)l*DIM*FFDIM, nullptr, FFb, MROWS, FFDIM, DIM, 1);
        sgemm<<<gD, 256>>>(FFb, W2 + (size_t)l*FFDIM*DIM, X, X, MROWS, DIM, FFDIM, 0);
    }
    ln_kernel<<<MROWS, 128>>>(X, lnfs, lnfb, (float*)d_out);
}

// round 4
// speedup vs baseline: 2.5159x; 1.4821x over previous
#include <cuda_runtime.h>
#include <cuda_bf16.h>
#include <math.h>

#define BATCH   8
#define SEQ     512
#define DIM     512
#define NHEADS  8
#define DHEAD   64
#define MEMN    4096
#define TOPK    32
#define FFDIM   2048
#define DEPTH   6
#define MROWS   (BATCH*SEQ)   /* 4096 */
#define NBH     (BATCH*NHEADS) /* 64 */
#define ATT_SCALE 0.125f      /* DH^-0.5 */

// ---------------- scratch (device globals; no allocation allowed) ----------
__device__ float g_X [MROWS*DIM];
__device__ float g_H [MROWS*DIM];
__device__ float g_Q [MROWS*DIM];
__device__ float g_K [MROWS*DIM];
__device__ float g_V [MROWS*DIM];
__device__ float g_AO[MROWS*DIM];
__device__ float g_FF[MROWS*FFDIM];
__device__ float g_S [(size_t)NBH*SEQ*MEMN];
__device__ float g_TV[(size_t)NBH*SEQ*TOPK];
__device__ int   g_TI[(size_t)NBH*SEQ*TOPK];

__device__ __forceinline__ float warp_sum(float v) {
    #pragma unroll
    for (int o = 16; o > 0; o >>= 1) v += __shfl_xor_sync(0xffffffffu, v, o);
    return v;
}

__device__ __forceinline__ float gelu_f(float v) {
    float c = v + 0.044715f * v * v * v;
    return 0.5f * v * (1.0f + tanhf(0.7978845608028654f * c));
}

// pack two floats as bf16x2 (x -> low half)
__device__ __forceinline__ unsigned bfpack(float x, float y) {
    __nv_bfloat162 p = __floats2bfloat162_rn(x, y);
    return *reinterpret_cast<unsigned*>(&p);
}
// hi part of a float in bf16 precision, returned as float
__device__ __forceinline__ float bfhi(float x) {
    return __bfloat162float(__float2bfloat16(x));
}

__device__ __forceinline__ void mma_bf16(float& d0, float& d1, float& d2, float& d3,
                                         unsigned a0, unsigned a1, unsigned a2, unsigned a3,
                                         unsigned b0, unsigned b1) {
    asm volatile(
        "mma.sync.aligned.m16n8k16.row.col.f32.bf16.bf16.f32 "
        "{%0,%1,%2,%3}, {%4,%5,%6,%7}, {%8,%9}, {%0,%1,%2,%3};\n"
        : "+f"(d0), "+f"(d1), "+f"(d2), "+f"(d3)
        : "r"(a0), "r"(a1), "r"(a2), "r"(a3), "r"(b0), "r"(b1));
}

// ---------------- LayerNorm -------------------------------------------------
__global__ void ln_kernel(const float* __restrict__ x,
                          const float* __restrict__ sc,
                          const float* __restrict__ bi,
                          float* __restrict__ out) {
    int row = blockIdx.x;
    int tid = threadIdx.x;
    const float4* xr = reinterpret_cast<const float4*>(x + (size_t)row * DIM);
    float4 v = xr[tid];
    float s  = v.x + v.y + v.z + v.w;
    float sq = v.x*v.x + v.y*v.y + v.z*v.z + v.w*v.w;
    __shared__ float ss[4], sqs[4];
    s  = warp_sum(s);
    sq = warp_sum(sq);
    int w = tid >> 5, lane = tid & 31;
    if (lane == 0) { ss[w] = s; sqs[w] = sq; }
    __syncthreads();
    float tot  = ss[0] + ss[1] + ss[2] + ss[3];
    float totq = sqs[0] + sqs[1] + sqs[2] + sqs[3];
    float mean = tot * (1.0f / DIM);
    float var  = totq * (1.0f / DIM) - mean * mean;
    float rstd = rsqrtf(var + 1e-5f);
    float4 sv = reinterpret_cast<const float4*>(sc)[tid];
    float4 bv = reinterpret_cast<const float4*>(bi)[tid];
    float4 o;
    o.x = (v.x - mean) * rstd * sv.x + bv.x;
    o.y = (v.y - mean) * rstd * sv.y + bv.y;
    o.z = (v.z - mean) * rstd * sv.z + bv.z;
    o.w = (v.w - mean) * rstd * sv.w + bv.w;
    reinterpret_cast<float4*>(out + (size_t)row * DIM)[tid] = o;
}

// ---- bf16-split tensor GEMM: C = act(A@B (+R)); 128x128x16 tile, 8 warps --
#define SW 136
__global__ __launch_bounds__(256)
void gemm_tc(const float* __restrict__ A, const float* __restrict__ B,
             const float* __restrict__ R, float* __restrict__ C,
             int M, int N, int K, int act) {
    __shared__ unsigned AsH[8*SW], AsL[8*SW];   // [k-pair j][row]
    __shared__ unsigned BsH[8*SW], BsL[8*SW];   // [k-pair j][col]
    int tid = threadIdx.x, lane = tid & 31, warp = tid >> 5;
    int wm = warp & 3, wn = warp >> 2;          // 4 x 2 warp grid -> 32x64 tiles
    int g = lane >> 2, tg = lane & 3;
    int bx = blockIdx.x, by = blockIdx.y;

    // A: row aRow, k-halves 8*(tid&1); j0 = 4*(tid&1)
    int aRow = tid >> 1, aJ0 = (tid & 1) * 4;
    // B: k-pair kp = tid>>5, 4 cols at (tid&31)*4
    int kp = tid >> 5, col4 = (tid & 31) * 4;

    const float* Ab = A + (size_t)(by * 128 + aRow) * K + aJ0 * 2;
    const float* Bb = B + (size_t)(kp*2) * N + bx * 128 + col4;

    float acc[2][8][4];
    #pragma unroll
    for (int mi = 0; mi < 2; mi++)
        #pragma unroll
        for (int ni = 0; ni < 8; ni++)
            #pragma unroll
            for (int r = 0; r < 4; r++) acc[mi][ni][r] = 0.f;

    for (int k0 = 0; k0 < K; k0 += 16) {
        // load + split A (8 floats/thread)
        float4 a0 = *reinterpret_cast<const float4*>(Ab + k0);
        float4 a1 = *reinterpret_cast<const float4*>(Ab + k0 + 4);
        float af8[8] = {a0.x,a0.y,a0.z,a0.w,a1.x,a1.y,a1.z,a1.w};
        #pragma unroll
        for (int jj = 0; jj < 4; jj++) {
            float x = af8[2*jj], y = af8[2*jj+1];
            float hx = bfhi(x), hy = bfhi(y);
            AsH[(aJ0+jj)*SW + aRow] = bfpack(hx, hy);
            AsL[(aJ0+jj)*SW + aRow] = bfpack(x - hx, y - hy);
        }
        // load + split B (2 rows x 4 cols/thread)
        float4 b0 = *reinterpret_cast<const float4*>(Bb + (size_t)k0 * N);
        float4 b1 = *reinterpret_cast<const float4*>(Bb + (size_t)(k0+1) * N);
        float b0a[4] = {b0.x,b0.y,b0.z,b0.w};
        float b1a[4] = {b1.x,b1.y,b1.z,b1.w};
        #pragma unroll
        for (int c = 0; c < 4; c++) {
            float x = b0a[c], y = b1a[c];
            float hx = bfhi(x), hy = bfhi(y);
            BsH[kp*SW + col4 + c] = bfpack(hx, hy);
            BsL[kp*SW + col4 + c] = bfpack(x - hx, y - hy);
        }
        __syncthreads();

        unsigned afH[2][4], afL[2][4];
        #pragma unroll
        for (int mi = 0; mi < 2; mi++) {
            int rb = wm*32 + mi*16 + g;
            afH[mi][0] = AsH[tg*SW + rb];     afL[mi][0] = AsL[tg*SW + rb];
            afH[mi][1] = AsH[tg*SW + rb+8];   afL[mi][1] = AsL[tg*SW + rb+8];
            afH[mi][2] = AsH[(tg+4)*SW + rb];   afL[mi][2] = AsL[(tg+4)*SW + rb];
            afH[mi][3] = AsH[(tg+4)*SW + rb+8]; afL[mi][3] = AsL[(tg+4)*SW + rb+8];
        }
        #pragma unroll
        for (int ni = 0; ni < 8; ni++) {
            int cb = wn*64 + ni*8 + g;
            unsigned bH0 = BsH[tg*SW + cb], bH1 = BsH[(tg+4)*SW + cb];
            unsigned bL0 = BsL[tg*SW + cb], bL1 = BsL[(tg+4)*SW + cb];
            #pragma unroll
            for (int mi = 0; mi < 2; mi++) {
                mma_bf16(acc[mi][ni][0], acc[mi][ni][1], acc[mi][ni][2], acc[mi][ni][3],
                         afH[mi][0], afH[mi][1], afH[mi][2], afH[mi][3], bL0, bL1);
                mma_bf16(acc[mi][ni][0], acc[mi][ni][1], acc[mi][ni][2], acc[mi][ni][3],
                         afL[mi][0], afL[mi][1], afL[mi][2], afL[mi][3], bH0, bH1);
                mma_bf16(acc[mi][ni][0], acc[mi][ni][1], acc[mi][ni][2], acc[mi][ni][3],
                         afH[mi][0], afH[mi][1], afH[mi][2], afH[mi][3], bH0, bH1);
            }
        }
        __syncthreads();
    }

    #pragma unroll
    for (int mi = 0; mi < 2; mi++) {
        #pragma unroll
        for (int ni = 0; ni < 8; ni++) {
            size_t row = (size_t)by*128 + wm*32 + mi*16 + g;
            size_t col = (size_t)bx*128 + wn*64 + ni*8 + tg*2;
            float v0 = acc[mi][ni][0], v1 = acc[mi][ni][1];
            float v2 = acc[mi][ni][2], v3 = acc[mi][ni][3];
            if (act) { v0 = gelu_f(v0); v1 = gelu_f(v1); v2 = gelu_f(v2); v3 = gelu_f(v3); }
            if (R) {
                float2 r0 = *reinterpret_cast<const float2*>(R + row*N + col);
                float2 r1 = *reinterpret_cast<const float2*>(R + (row+8)*N + col);
                v0 += r0.x; v1 += r0.y; v2 += r1.x; v3 += r1.y;
            }
            *reinterpret_cast<float2*>(C + row*N + col)     = make_float2(v0, v1);
            *reinterpret_cast<float2*>(C + (row+8)*N + col) = make_float2(v2, v3);
        }
    }
}

// -------- bf16-split KNN sim (NT): S[bh,i,m] = scale * q . mk --------------
__global__ __launch_bounds__(256)
void knn_sim_tc(const float* __restrict__ Q, const float* __restrict__ MK,
                float* __restrict__ S) {
    __shared__ unsigned AsH[8*SW], AsL[8*SW];   // [d-pair][i-row]
    __shared__ unsigned BsH[8*SW], BsL[8*SW];   // [d-pair][m-col]
    int tid = threadIdx.x, lane = tid & 31, warp = tid >> 5;
    int wm = warp & 3, wn = warp >> 2;
    int g = lane >> 2, tg = lane & 3;
    int bh = blockIdx.z, b = bh >> 3, h = bh & 7;

    int lRow = tid >> 1, lJ0 = (tid & 1) * 4;
    const float* Qb = Q + (size_t)(b*SEQ + blockIdx.y*128 + lRow) * DIM + h*DHEAD + lJ0*2;
    const float* Mb = MK + (size_t)(b*MEMN + blockIdx.x*128 + lRow) * DHEAD + lJ0*2;

    float acc[2][8][4];
    #pragma unroll
    for (int mi = 0; mi < 2; mi++)
        #pragma unroll
        for (int ni = 0; ni < 8; ni++)
            #pragma unroll
            for (int r = 0; r < 4; r++) acc[mi][ni][r] = 0.f;

    for (int k0 = 0; k0 < DHEAD; k0 += 16) {
        float4 a0 = *reinterpret_cast<const float4*>(Qb + k0);
        float4 a1 = *reinterpret_cast<const float4*>(Qb + k0 + 4);
        float af8[8] = {a0.x,a0.y,a0.z,a0.w,a1.x,a1.y,a1.z,a1.w};
        float4 b0 = *reinterpret_cast<const float4*>(Mb + k0);
        float4 b1 = *reinterpret_cast<const float4*>(Mb + k0 + 4);
        float bf8[8] = {b0.x,b0.y,b0.z,b0.w,b1.x,b1.y,b1.z,b1.w};
        #pragma unroll
        for (int jj = 0; jj < 4; jj++) {
            float x = af8[2*jj], y = af8[2*jj+1];
            float hx = bfhi(x), hy = bfhi(y);
            AsH[(lJ0+jj)*SW + lRow] = bfpack(hx, hy);
            AsL[(lJ0+jj)*SW + lRow] = bfpack(x - hx, y - hy);
            float u = bf8[2*jj], v = bf8[2*jj+1];
            float hu = bfhi(u), hv = bfhi(v);
            BsH[(lJ0+jj)*SW + lRow] = bfpack(hu, hv);
            BsL[(lJ0+jj)*SW + lRow] = bfpack(u - hu, v - hv);
        }
        __syncthreads();

        unsigned afH[2][4], afL[2][4];
        #pragma unroll
        for (int mi = 0; mi < 2; mi++) {
            int rb = wm*32 + mi*16 + g;
            afH[mi][0] = AsH[tg*SW + rb];     afL[mi][0] = AsL[tg*SW + rb];
            afH[mi][1] = AsH[tg*SW + rb+8];   afL[mi][1] = AsL[tg*SW + rb+8];
            afH[mi][2] = AsH[(tg+4)*SW + rb];   afL[mi][2] = AsL[(tg+4)*SW + rb];
            afH[mi][3] = AsH[(tg+4)*SW + rb+8]; afL[mi][3] = AsL[(tg+4)*SW + rb+8];
        }
        #pragma unroll
        for (int ni = 0; ni < 8; ni++) {
            int cb = wn*64 + ni*8 + g;
            unsigned bH0 = BsH[tg*SW + cb], bH1 = BsH[(tg+4)*SW + cb];
            unsigned bL0 = BsL[tg*SW + cb], bL1 = BsL[(tg+4)*SW + cb];
            #pragma unroll
            for (int mi = 0; mi < 2; mi++) {
                mma_bf16(acc[mi][ni][0], acc[mi][ni][1], acc[mi][ni][2], acc[mi][ni][3],
                         afH[mi][0], afH[mi][1], afH[mi][2], afH[mi][3], bL0, bL1);
                mma_bf16(acc[mi][ni][0], acc[mi][ni][1], acc[mi][ni][2], acc[mi][ni][3],
                         afL[mi][0], afL[mi][1], afL[mi][2], afL[mi][3], bH0, bH1);
                mma_bf16(acc[mi][ni][0], acc[mi][ni][1], acc[mi][ni][2], acc[mi][ni][3],
                         afH[mi][0], afH[mi][1], afH[mi][2], afH[mi][3], bH0, bH1);
            }
        }
        __syncthreads();
    }

    #pragma unroll
    for (int mi = 0; mi < 2; mi++) {
        #pragma unroll
        for (int ni = 0; ni < 8; ni++) {
            size_t iG = (size_t)blockIdx.y*128 + wm*32 + mi*16 + g;
            size_t mG = (size_t)blockIdx.x*128 + wn*64 + ni*8 + tg*2;
            *reinterpret_cast<float2*>(S + ((size_t)bh*SEQ + iG)*MEMN + mG) =
                make_float2(acc[mi][ni][0]*ATT_SCALE, acc[mi][ni][1]*ATT_SCALE);
            *reinterpret_cast<float2*>(S + ((size_t)bh*SEQ + iG + 8)*MEMN + mG) =
                make_float2(acc[mi][ni][2]*ATT_SCALE, acc[mi][ni][3]*ATT_SCALE);
        }
    }
}

// -------- top-32 per (bh,i) -------------------------------------------------
__global__ __launch_bounds__(256)
void topk_kernel(const float* __restrict__ S, float* __restrict__ TV,
                 int* __restrict__ TI) {
    int i = blockIdx.x, bh = blockIdx.y;
    const float* row = S + ((size_t)bh*SEQ + i)*MEMN;
    __shared__ float sv[MEMN];
    __shared__ float wv[8];
    __shared__ int   wi[8];
    __shared__ int wini;
    int tid = threadIdx.x;

    float lmax = -1e30f; int lidx = 0;
    #pragma unroll 4
    for (int j = 0; j < 16; j++) {
        int m = tid + 256*j;
        float v = row[m];
        sv[m] = v;
        if (v > lmax) { lmax = v; lidx = m; }
    }
    for (int t = 0; t < TOPK; t++) {
        float v = lmax; int idx = lidx;
        #pragma unroll
        for (int o = 16; o > 0; o >>= 1) {
            float ov = __shfl_xor_sync(0xffffffffu, v, o);
            int   oi = __shfl_xor_sync(0xffffffffu, idx, o);
            if (ov > v) { v = ov; idx = oi; }
        }
        if ((tid & 31) == 0) { wv[tid>>5] = v; wi[tid>>5] = idx; }
        __syncthreads();
        if (tid < 32) {
            float v2 = (tid < 8) ? wv[tid] : -1e30f;
            int   i2 = (tid < 8) ? wi[tid] : 0;
            #pragma unroll
            for (int o = 4; o > 0; o >>= 1) {
                float ov = __shfl_xor_sync(0xffffffffu, v2, o);
                int   oi = __shfl_xor_sync(0xffffffffu, i2, o);
                if (ov > v2) { v2 = ov; i2 = oi; }
            }
            if (tid == 0) {
                wini = i2;
                TV[((size_t)bh*SEQ + i)*TOPK + t] = v2;
                TI[((size_t)bh*SEQ + i)*TOPK + t] = i2;
            }
        }
        __syncthreads();
        int widx = wini;
        if ((widx & 255) == tid) {
            sv[widx] = -1e30f;
            lmax = -1e30f; lidx = 0;
            #pragma unroll 4
            for (int j = 0; j < 16; j++) {
                int m = tid + 256*j;
                float vv = sv[m];
                if (vv > lmax) { lmax = vv; lidx = m; }
            }
        }
    }
}

// ---------------- local causal attention -----------------------------------
__global__ __launch_bounds__(128)
void attn_local(const float* __restrict__ Q, const float* __restrict__ Kp,
                const float* __restrict__ V, float* __restrict__ O) {
    int i = blockIdx.x, h = blockIdx.y, b = blockIdx.z;
    int tid = threadIdx.x, lane = tid & 31, w = tid >> 5;
    __shared__ float qs[DHEAD];
    __shared__ float p[SEQ];
    __shared__ float red[128];

    if (tid < DHEAD) qs[tid] = Q[((size_t)(b*SEQ + i)) * DIM + h*DHEAD + tid];
    __syncthreads();

    for (int j = w; j <= i; j += 4) {
        const float* kr = Kp + ((size_t)(b*SEQ + j)) * DIM + h*DHEAD;
        float part = qs[lane] * kr[lane] + qs[lane+32] * kr[lane+32];
        part = warp_sum(part);
        if (lane == 0) p[j] = part * ATT_SCALE;
    }
    __syncthreads();

    float lm = -1e30f;
    for (int j = tid; j <= i; j += 128) lm = fmaxf(lm, p[j]);
    red[tid] = lm; __syncthreads();
    for (int s = 64; s > 0; s >>= 1) { if (tid < s) red[tid] = fmaxf(red[tid], red[tid+s]); __syncthreads(); }
    float mx = red[0]; __syncthreads();
    float ls = 0.f;
    for (int j = tid; j <= i; j += 128) { float e = __expf(p[j] - mx); p[j] = e; ls += e; }
    red[tid] = ls; __syncthreads();
    for (int s = 64; s > 0; s >>= 1) { if (tid < s) red[tid] += red[tid+s]; __syncthreads(); }
    float inv = 1.0f / red[0]; __syncthreads();

    int part2 = tid >> 6, d = tid & 63;
    float acc = 0.f;
    for (int j = part2; j <= i; j += 2)
        acc += p[j] * V[((size_t)(b*SEQ + j)) * DIM + h*DHEAD + d];
    red[tid] = acc; __syncthreads();
    if (part2 == 0)
        O[((size_t)(b*SEQ + i)) * DIM + h*DHEAD + d] = (red[tid] + red[tid+64]) * inv;
}

// -------- KNN attention using precomputed top-32 ---------------------------
__global__ __launch_bounds__(128)
void attn_knn2(const float* __restrict__ Q, const float* __restrict__ Kp,
               const float* __restrict__ V, const float* __restrict__ MV,
               const float* __restrict__ TV, const int* __restrict__ TI,
               float* __restrict__ O) {
    int i = blockIdx.x, h = blockIdx.y, b = blockIdx.z;
    int bh = b*NHEADS + h;
    int tid = threadIdx.x, lane = tid & 31, w = tid >> 5;
    __shared__ float qs[DHEAD];
    __shared__ float p[SEQ];
    __shared__ float tv[TOPK];
    __shared__ int   ti[TOPK];
    __shared__ float red[128];

    if (tid < DHEAD) qs[tid] = Q[((size_t)(b*SEQ + i)) * DIM + h*DHEAD + tid];
    if (tid >= 64 && tid < 64 + TOPK) {
        int t = tid - 64;
        tv[t] = TV[((size_t)bh*SEQ + i)*TOPK + t];
        ti[t] = TI[((size_t)bh*SEQ + i)*TOPK + t];
    }
    __syncthreads();

    for (int j = w; j <= i; j += 4) {
        const float* kr = Kp + ((size_t)(b*SEQ + j)) * DIM + h*DHEAD;
        float part = qs[lane] * kr[lane] + qs[lane+32] * kr[lane+32];
        part = warp_sum(part);
        if (lane == 0) p[j] = part * ATT_SCALE;
    }
    __syncthreads();

    float lm = -1e30f;
    for (int j = tid; j <= i; j += 128) lm = fmaxf(lm, p[j]);
    if (tid < TOPK) lm = fmaxf(lm, tv[tid]);
    red[tid] = lm; __syncthreads();
    for (int s = 64; s > 0; s >>= 1) { if (tid < s) red[tid] = fmaxf(red[tid], red[tid+s]); __syncthreads(); }
    float mx = red[0]; __syncthreads();
    float ls = 0.f;
    for (int j = tid; j <= i; j += 128) { float e = __expf(p[j] - mx); p[j] = e; ls += e; }
    if (tid < TOPK) { float e = __expf(tv[tid] - mx); tv[tid] = e; ls += e; }
    red[tid] = ls; __syncthreads();
    for (int s = 64; s > 0; s >>= 1) { if (tid < s) red[tid] += red[tid+s]; __syncthreads(); }
    float inv = 1.0f / red[0]; __syncthreads();

    int part2 = tid >> 6, d = tid & 63;
    float acc = 0.f;
    if (part2 == 0) {
        const float* mvb = MV + (size_t)b * MEMN * DHEAD;
        #pragma unroll
        for (int t = 0; t < TOPK; t++)
            acc += tv[t] * mvb[(size_t)ti[t] * DHEAD + d];
    }
    for (int j = part2; j <= i; j += 2)
        acc += p[j] * V[((size_t)(b*SEQ + j)) * DIM + h*DHEAD + d];
    red[tid] = acc; __syncthreads();
    if (part2 == 0)
        O[((size_t)(b*SEQ + i)) * DIM + h*DHEAD + d] = (red[tid] + red[tid+64]) * inv;
}

// ---------------- host orchestration --------------------------------------
extern "C" void kernel_launch(void* const* d_in, const int* in_sizes, int n_in,
                              void* d_out, int out_size) {
    const float* x     = (const float*)d_in[0];
    const float* Wq    = (const float*)d_in[1];
    const float* Wk    = (const float*)d_in[2];
    const float* Wv    = (const float*)d_in[3];
    const float* Wo    = (const float*)d_in[4];
    const float* ln1s  = (const float*)d_in[5];
    const float* ln1b  = (const float*)d_in[6];
    const float* ln2s  = (const float*)d_in[7];
    const float* ln2b  = (const float*)d_in[8];
    const float* W1    = (const float*)d_in[9];
    const float* W2    = (const float*)d_in[10];
    const float* lnfs  = (const float*)d_in[11];
    const float* lnfb  = (const float*)d_in[12];
    const float* mem_k = (const float*)d_in[13];
    const float* mem_v = (const float*)d_in[14];

    float *X, *H, *Q, *K, *V, *AO, *FFb, *S, *TV;
    int *TI;
    cudaGetSymbolAddress((void**)&X,  g_X);
    cudaGetSymbolAddress((void**)&H,  g_H);
    cudaGetSymbolAddress((void**)&Q,  g_Q);
    cudaGetSymbolAddress((void**)&K,  g_K);
    cudaGetSymbolAddress((void**)&V,  g_V);
    cudaGetSymbolAddress((void**)&AO, g_AO);
    cudaGetSymbolAddress((void**)&FFb, g_FF);
    cudaGetSymbolAddress((void**)&S,  g_S);
    cudaGetSymbolAddress((void**)&TV, g_TV);
    cudaGetSymbolAddress((void**)&TI, g_TI);

    cudaMemcpyAsync(X, x, sizeof(float) * MROWS * DIM, cudaMemcpyDeviceToDevice);

    dim3 gD(DIM/128, MROWS/128);
    dim3 gF(FFDIM/128, MROWS/128);
    dim3 gAtt(SEQ, NHEADS, BATCH);
    dim3 gSim(MEMN/128, SEQ/128, NBH);
    dim3 gTop(SEQ, NBH);

    int mi = 0;
    for (int l = 0; l < DEPTH; l++) {
        ln_kernel<<<MROWS, 128>>>(X, ln1s + l*DIM, ln1b + l*DIM, H);
        gemm_tc<<<gD, 256>>>(H, Wq + (size_t)l*DIM*DIM, nullptr, Q, MROWS, DIM, DIM, 0);
        gemm_tc<<<gD, 256>>>(H, Wk + (size_t)l*DIM*DIM, nullptr, K, MROWS, DIM, DIM, 0);
        gemm_tc<<<gD, 256>>>(H, Wv + (size_t)l*DIM*DIM, nullptr, V, MROWS, DIM, DIM, 0);
        if (l == 3 || l == 4) {
            const float* MK = mem_k + (size_t)mi * BATCH * MEMN * DHEAD;
            const float* MV = mem_v + (size_t)mi * BATCH * MEMN * DHEAD;
            knn_sim_tc<<<gSim, 256>>>(Q, MK, S);
            topk_kernel<<<gTop, 256>>>(S, TV, TI);
            attn_knn2<<<gAtt, 128>>>(Q, K, V, MV, TV, TI, AO);
            mi++;
        } else {
            attn_local<<<gAtt, 128>>>(Q, K, V, AO);
        }
        gemm_tc<<<gD, 256>>>(AO, Wo + (size_t)l*DIM*DIM, X, X, MROWS, DIM, DIM, 0);
        ln_kernel<<<MROWS, 128>>>(X, ln2s + l*DIM, ln2b + l*DIM, H);
        gemm_tc<<<gF, 256>>>(H, W1 + (size_t)l*DIM*FFDIM, nullptr, FFb, MROWS, FFDIM, DIM, 1);
        gemm_tc<<<gD, 256>>>(FFb, W2 + (size_t)l*FFDIM*DIM, X, X, MROWS, DIM, FFDIM, 0);
    }
    ln_kernel<<<MROWS, 128>>>(X, lnfs, lnfb, (float*)d_out);
}

// round 5
// speedup vs baseline: 3.5997x; 1.4307x over previous
#include <cuda_runtime.h>
#include <cuda_bf16.h>
#include <math.h>

#define BATCH   8
#define SEQ     512
#define DIM     512
#define NHEADS  8
#define DHEAD   64
#define MEMN    4096
#define TOPK    32
#define FFDIM   2048
#define DEPTH   6
#define MROWS   (BATCH*SEQ)    /* 4096 */
#define NBH     (BATCH*NHEADS) /* 64 */
#define ATT_SCALE 0.125f

// ---------------- scratch (device globals; no allocation allowed) ----------
__device__ float g_X [MROWS*DIM];
__device__ float g_H [MROWS*DIM];
__device__ float g_Q [MROWS*DIM];
__device__ float g_K [MROWS*DIM];
__device__ float g_V [MROWS*DIM];
__device__ float g_AO[MROWS*DIM];
__device__ float g_FF[MROWS*FFDIM];
__device__ float g_S [(size_t)NBH*SEQ*MEMN];   // knn sims
__device__ float g_P [(size_t)NBH*SEQ*SEQ];    // local sims / probs
__device__ float g_TV[(size_t)NBH*SEQ*TOPK];
__device__ int   g_TI[(size_t)NBH*SEQ*TOPK];

__device__ __forceinline__ float warp_sum(float v) {
    #pragma unroll
    for (int o = 16; o > 0; o >>= 1) v += __shfl_xor_sync(0xffffffffu, v, o);
    return v;
}
__device__ __forceinline__ float gelu_f(float v) {
    float c = v + 0.044715f * v * v * v;
    return 0.5f * v * (1.0f + tanhf(0.7978845608028654f * c));
}
__device__ __forceinline__ unsigned bfpack(float x, float y) {
    __nv_bfloat162 p = __floats2bfloat162_rn(x, y);
    return *reinterpret_cast<unsigned*>(&p);
}
__device__ __forceinline__ float bfhi(float x) {
    return __bfloat162float(__float2bfloat16(x));
}
__device__ __forceinline__ void mma_bf16(float& d0, float& d1, float& d2, float& d3,
                                         unsigned a0, unsigned a1, unsigned a2, unsigned a3,
                                         unsigned b0, unsigned b1) {
    asm volatile(
        "mma.sync.aligned.m16n8k16.row.col.f32.bf16.bf16.f32 "
        "{%0,%1,%2,%3}, {%4,%5,%6,%7}, {%8,%9}, {%0,%1,%2,%3};\n"
        : "+f"(d0), "+f"(d1), "+f"(d2), "+f"(d3)
        : "r"(a0), "r"(a1), "r"(a2), "r"(a3), "r"(b0), "r"(b1));
}

// ---------------- LayerNorm -------------------------------------------------
__global__ void ln_kernel(const float* __restrict__ x,
                          const float* __restrict__ sc,
                          const float* __restrict__ bi,
                          float* __restrict__ out) {
    int row = blockIdx.x;
    int tid = threadIdx.x;
    const float4* xr = reinterpret_cast<const float4*>(x + (size_t)row * DIM);
    float4 v = xr[tid];
    float s  = v.x + v.y + v.z + v.w;
    float sq = v.x*v.x + v.y*v.y + v.z*v.z + v.w*v.w;
    __shared__ float ss[4], sqs[4];
    s  = warp_sum(s);
    sq = warp_sum(sq);
    int w = tid >> 5, lane = tid & 31;
    if (lane == 0) { ss[w] = s; sqs[w] = sq; }
    __syncthreads();
    float tot  = ss[0] + ss[1] + ss[2] + ss[3];
    float totq = sqs[0] + sqs[1] + sqs[2] + sqs[3];
    float mean = tot * (1.0f / DIM);
    float var  = totq * (1.0f / DIM) - mean * mean;
    float rstd = rsqrtf(var + 1e-5f);
    float4 sv = reinterpret_cast<const float4*>(sc)[tid];
    float4 bv = reinterpret_cast<const float4*>(bi)[tid];
    float4 o;
    o.x = (v.x - mean) * rstd * sv.x + bv.x;
    o.y = (v.y - mean) * rstd * sv.y + bv.y;
    o.z = (v.z - mean) * rstd * sv.z + bv.z;
    o.w = (v.w - mean) * rstd * sv.w + bv.w;
    reinterpret_cast<float4*>(out + (size_t)row * DIM)[tid] = o;
}

// ---- bf16-split tensor GEMM body: C = act(A@B (+R)); 128x128x16 tile ------
#define SW 136
__device__ __forceinline__ void gemm_body(
    const float* __restrict__ A, const float* __restrict__ B,
    const float* __restrict__ R, float* __restrict__ C,
    int N, int K, int act, int bx, int by)
{
    __shared__ unsigned AsH[8*SW], AsL[8*SW];
    __shared__ unsigned BsH[8*SW], BsL[8*SW];
    int tid = threadIdx.x, lane = tid & 31, warp = tid >> 5;
    int wm = warp & 3, wn = warp >> 2;
    int g = lane >> 2, tg = lane & 3;

    int aRow = tid >> 1, aJ0 = (tid & 1) * 4;
    int kp = tid >> 5, col4 = (tid & 31) * 4;

    const float* Ab = A + (size_t)(by * 128 + aRow) * K + aJ0 * 2;
    const float* Bb = B + (size_t)(kp*2) * N + bx * 128 + col4;

    float acc[2][8][4];
    #pragma unroll
    for (int mi = 0; mi < 2; mi++)
        #pragma unroll
        for (int ni = 0; ni < 8; ni++)
            #pragma unroll
            for (int r = 0; r < 4; r++) acc[mi][ni][r] = 0.f;

    for (int k0 = 0; k0 < K; k0 += 16) {
        float4 a0 = *reinterpret_cast<const float4*>(Ab + k0);
        float4 a1 = *reinterpret_cast<const float4*>(Ab + k0 + 4);
        float af8[8] = {a0.x,a0.y,a0.z,a0.w,a1.x,a1.y,a1.z,a1.w};
        #pragma unroll
        for (int jj = 0; jj < 4; jj++) {
            float x = af8[2*jj], y = af8[2*jj+1];
            float hx = bfhi(x), hy = bfhi(y);
            AsH[(aJ0+jj)*SW + aRow] = bfpack(hx, hy);
            AsL[(aJ0+jj)*SW + aRow] = bfpack(x - hx, y - hy);
        }
        float4 b0 = *reinterpret_cast<const float4*>(Bb + (size_t)k0 * N);
        float4 b1 = *reinterpret_cast<const float4*>(Bb + (size_t)(k0+1) * N);
        float b0a[4] = {b0.x,b0.y,b0.z,b0.w};
        float b1a[4] = {b1.x,b1.y,b1.z,b1.w};
        #pragma unroll
        for (int c = 0; c < 4; c++) {
            float x = b0a[c], y = b1a[c];
            float hx = bfhi(x), hy = bfhi(y);
            BsH[kp*SW + col4 + c] = bfpack(hx, hy);
            BsL[kp*SW + col4 + c] = bfpack(x - hx, y - hy);
        }
        __syncthreads();

        unsigned afH[2][4], afL[2][4];
        #pragma unroll
        for (int mi = 0; mi < 2; mi++) {
            int rb = wm*32 + mi*16 + g;
            afH[mi][0] = AsH[tg*SW + rb];       afL[mi][0] = AsL[tg*SW + rb];
            afH[mi][1] = AsH[tg*SW + rb+8];     afL[mi][1] = AsL[tg*SW + rb+8];
            afH[mi][2] = AsH[(tg+4)*SW + rb];   afL[mi][2] = AsL[(tg+4)*SW + rb];
            afH[mi][3] = AsH[(tg+4)*SW + rb+8]; afL[mi][3] = AsL[(tg+4)*SW + rb+8];
        }
        #pragma unroll
        for (int ni = 0; ni < 8; ni++) {
            int cb = wn*64 + ni*8 + g;
            unsigned bH0 = BsH[tg*SW + cb], bH1 = BsH[(tg+4)*SW + cb];
            unsigned bL0 = BsL[tg*SW + cb], bL1 = BsL[(tg+4)*SW + cb];
            #pragma unroll
            for (int mi = 0; mi < 2; mi++) {
                mma_bf16(acc[mi][ni][0], acc[mi][ni][1], acc[mi][ni][2], acc[mi][ni][3],
                         afH[mi][0], afH[mi][1], afH[mi][2], afH[mi][3], bL0, bL1);
                mma_bf16(acc[mi][ni][0], acc[mi][ni][1], acc[mi][ni][2], acc[mi][ni][3],
                         afL[mi][0], afL[mi][1], afL[mi][2], afL[mi][3], bH0, bH1);
                mma_bf16(acc[mi][ni][0], acc[mi][ni][1], acc[mi][ni][2], acc[mi][ni][3],
                         afH[mi][0], afH[mi][1], afH[mi][2], afH[mi][3], bH0, bH1);
            }
        }
        __syncthreads();
    }

    #pragma unroll
    for (int mi = 0; mi < 2; mi++) {
        #pragma unroll
        for (int ni = 0; ni < 8; ni++) {
            size_t row = (size_t)by*128 + wm*32 + mi*16 + g;
            size_t col = (size_t)bx*128 + wn*64 + ni*8 + tg*2;
            float v0 = acc[mi][ni][0], v1 = acc[mi][ni][1];
            float v2 = acc[mi][ni][2], v3 = acc[mi][ni][3];
            if (act) { v0 = gelu_f(v0); v1 = gelu_f(v1); v2 = gelu_f(v2); v3 = gelu_f(v3); }
            if (R) {
                float2 r0 = *reinterpret_cast<const float2*>(R + row*N + col);
                float2 r1 = *reinterpret_cast<const float2*>(R + (row+8)*N + col);
                v0 += r0.x; v1 += r0.y; v2 += r1.x; v3 += r1.y;
            }
            *reinterpret_cast<float2*>(C + row*N + col)     = make_float2(v0, v1);
            *reinterpret_cast<float2*>(C + (row+8)*N + col) = make_float2(v2, v3);
        }
    }
}

__global__ __launch_bounds__(256)
void gemm_tc(const float* __restrict__ A, const float* __restrict__ B,
             const float* __restrict__ R, float* __restrict__ C,
             int N, int K, int act) {
    gemm_body(A, B, R, C, N, K, act, blockIdx.x, blockIdx.y);
}

// fused QKV: blockIdx.z selects weight/output
__global__ __launch_bounds__(256)
void gemm_qkv(const float* __restrict__ H,
              const float* __restrict__ Wq, const float* __restrict__ Wk,
              const float* __restrict__ Wv,
              float* __restrict__ Q, float* __restrict__ K, float* __restrict__ V) {
    const float* B = (blockIdx.z == 0) ? Wq : (blockIdx.z == 1) ? Wk : Wv;
    float* C = (blockIdx.z == 0) ? Q : (blockIdx.z == 1) ? K : V;
    gemm_body(H, B, nullptr, C, DIM, DIM, 0, blockIdx.x, blockIdx.y);
}

// -------- bf16-split KNN sim (NT): S[bh,i,m] = scale * q . mk --------------
__global__ __launch_bounds__(256)
void knn_sim_tc(const float* __restrict__ Q, const float* __restrict__ MK,
                float* __restrict__ S) {
    __shared__ unsigned AsH[8*SW], AsL[8*SW];
    __shared__ unsigned BsH[8*SW], BsL[8*SW];
    int tid = threadIdx.x, lane = tid & 31, warp = tid >> 5;
    int wm = warp & 3, wn = warp >> 2;
    int g = lane >> 2, tg = lane & 3;
    int bh = blockIdx.z, b = bh >> 3, h = bh & 7;

    int lRow = tid >> 1, lJ0 = (tid & 1) * 4;
    const float* Qb = Q + (size_t)(b*SEQ + blockIdx.y*128 + lRow) * DIM + h*DHEAD + lJ0*2;
    const float* Mb = MK + (size_t)(b*MEMN + blockIdx.x*128 + lRow) * DHEAD + lJ0*2;

    float acc[2][8][4];
    #pragma unroll
    for (int mi = 0; mi < 2; mi++)
        #pragma unroll
        for (int ni = 0; ni < 8; ni++)
            #pragma unroll
            for (int r = 0; r < 4; r++) acc[mi][ni][r] = 0.f;

    for (int k0 = 0; k0 < DHEAD; k0 += 16) {
        float4 a0 = *reinterpret_cast<const float4*>(Qb + k0);
        float4 a1 = *reinterpret_cast<const float4*>(Qb + k0 + 4);
        float af8[8] = {a0.x,a0.y,a0.z,a0.w,a1.x,a1.y,a1.z,a1.w};
        float4 b0 = *reinterpret_cast<const float4*>(Mb + k0);
        float4 b1 = *reinterpret_cast<const float4*>(Mb + k0 + 4);
        float bf8[8] = {b0.x,b0.y,b0.z,b0.w,b1.x,b1.y,b1.z,b1.w};
        #pragma unroll
        for (int jj = 0; jj < 4; jj++) {
            float x = af8[2*jj], y = af8[2*jj+1];
            float hx = bfhi(x), hy = bfhi(y);
            AsH[(lJ0+jj)*SW + lRow] = bfpack(hx, hy);
            AsL[(lJ0+jj)*SW + lRow] = bfpack(x - hx, y - hy);
            float u = bf8[2*jj], v = bf8[2*jj+1];
            float hu = bfhi(u), hv = bfhi(v);
            BsH[(lJ0+jj)*SW + lRow] = bfpack(hu, hv);
            BsL[(lJ0+jj)*SW + lRow] = bfpack(u - hu, v - hv);
        }
        __syncthreads();
        unsigned afH[2][4], afL[2][4];
        #pragma unroll
        for (int mi = 0; mi < 2; mi++) {
            int rb = wm*32 + mi*16 + g;
            afH[mi][0] = AsH[tg*SW + rb];       afL[mi][0] = AsL[tg*SW + rb];
            afH[mi][1] = AsH[tg*SW + rb+8];     afL[mi][1] = AsL[tg*SW + rb+8];
            afH[mi][2] = AsH[(tg+4)*SW + rb];   afL[mi][2] = AsL[(tg+4)*SW + rb];
            afH[mi][3] = AsH[(tg+4)*SW + rb+8]; afL[mi][3] = AsL[(tg+4)*SW + rb+8];
        }
        #pragma unroll
        for (int ni = 0; ni < 8; ni++) {
            int cb = wn*64 + ni*8 + g;
            unsigned bH0 = BsH[tg*SW + cb], bH1 = BsH[(tg+4)*SW + cb];
            unsigned bL0 = BsL[tg*SW + cb], bL1 = BsL[(tg+4)*SW + cb];
            #pragma unroll
            for (int mi = 0; mi < 2; mi++) {
                mma_bf16(acc[mi][ni][0], acc[mi][ni][1], acc[mi][ni][2], acc[mi][ni][3],
                         afH[mi][0], afH[mi][1], afH[mi][2], afH[mi][3], bL0, bL1);
                mma_bf16(acc[mi][ni][0], acc[mi][ni][1], acc[mi][ni][2], acc[mi][ni][3],
                         afL[mi][0], afL[mi][1], afL[mi][2], afL[mi][3], bH0, bH1);
                mma_bf16(acc[mi][ni][0], acc[mi][ni][1], acc[mi][ni][2], acc[mi][ni][3],
                         afH[mi][0], afH[mi][1], afH[mi][2], afH[mi][3], bH0, bH1);
            }
        }
        __syncthreads();
    }

    #pragma unroll
    for (int mi = 0; mi < 2; mi++) {
        #pragma unroll
        for (int ni = 0; ni < 8; ni++) {
            size_t iG = (size_t)blockIdx.y*128 + wm*32 + mi*16 + g;
            size_t mG = (size_t)blockIdx.x*128 + wn*64 + ni*8 + tg*2;
            *reinterpret_cast<float2*>(S + ((size_t)bh*SEQ + iG)*MEMN + mG) =
                make_float2(acc[mi][ni][0]*ATT_SCALE, acc[mi][ni][1]*ATT_SCALE);
            *reinterpret_cast<float2*>(S + ((size_t)bh*SEQ + iG + 8)*MEMN + mG) =
                make_float2(acc[mi][ni][2]*ATT_SCALE, acc[mi][ni][3]*ATT_SCALE);
        }
    }
}

// -------- bf16-split local sim (NT): P[bh,i,j] = scale * q . k -------------
__global__ __launch_bounds__(256)
void sim_local_tc(const float* __restrict__ Q, const float* __restrict__ Km,
                  float* __restrict__ P) {
    if (blockIdx.x > blockIdx.y) return;   // fully masked key tile
    __shared__ unsigned AsH[8*SW], AsL[8*SW];
    __shared__ unsigned BsH[8*SW], BsL[8*SW];
    int tid = threadIdx.x, lane = tid & 31, warp = tid >> 5;
    int wm = warp & 3, wn = warp >> 2;
    int g = lane >> 2, tg = lane & 3;
    int bh = blockIdx.z, b = bh >> 3, h = bh & 7;

    int lRow = tid >> 1, lJ0 = (tid & 1) * 4;
    const float* Qb = Q + (size_t)(b*SEQ + blockIdx.y*128 + lRow) * DIM + h*DHEAD + lJ0*2;
    const float* Mb = Km + (size_t)(b*SEQ + blockIdx.x*128 + lRow) * DIM + h*DHEAD + lJ0*2;

    float acc[2][8][4];
    #pragma unroll
    for (int mi = 0; mi < 2; mi++)
        #pragma unroll
        for (int ni = 0; ni < 8; ni++)
            #pragma unroll
            for (int r = 0; r < 4; r++) acc[mi][ni][r] = 0.f;

    for (int k0 = 0; k0 < DHEAD; k0 += 16) {
        float4 a0 = *reinterpret_cast<const float4*>(Qb + k0);
        float4 a1 = *reinterpret_cast<const float4*>(Qb + k0 + 4);
        float af8[8] = {a0.x,a0.y,a0.z,a0.w,a1.x,a1.y,a1.z,a1.w};
        float4 b0 = *reinterpret_cast<const float4*>(Mb + k0);
        float4 b1 = *reinterpret_cast<const float4*>(Mb + k0 + 4);
        float bf8[8] = {b0.x,b0.y,b0.z,b0.w,b1.x,b1.y,b1.z,b1.w};
        #pragma unroll
        for (int jj = 0; jj < 4; jj++) {
            float x = af8[2*jj], y = af8[2*jj+1];
            float hx = bfhi(x), hy = bfhi(y);
            AsH[(lJ0+jj)*SW + lRow] = bfpack(hx, hy);
            AsL[(lJ0+jj)*SW + lRow] = bfpack(x - hx, y - hy);
            float u = bf8[2*jj], v = bf8[2*jj+1];
            float hu = bfhi(u), hv = bfhi(v);
            BsH[(lJ0+jj)*SW + lRow] = bfpack(hu, hv);
            BsL[(lJ0+jj)*SW + lRow] = bfpack(u - hu, v - hv);
        }
        __syncthreads();
        unsigned afH[2][4], afL[2][4];
        #pragma unroll
        for (int mi = 0; mi < 2; mi++) {
            int rb = wm*32 + mi*16 + g;
            afH[mi][0] = AsH[tg*SW + rb];       afL[mi][0] = AsL[tg*SW + rb];
            afH[mi][1] = AsH[tg*SW + rb+8];     afL[mi][1] = AsL[tg*SW + rb+8];
            afH[mi][2] = AsH[(tg+4)*SW + rb];   afL[mi][2] = AsL[(tg+4)*SW + rb];
            afH[mi][3] = AsH[(tg+4)*SW + rb+8]; afL[mi][3] = AsL[(tg+4)*SW + rb+8];
        }
        #pragma unroll
        for (int ni = 0; ni < 8; ni++) {
            int cb = wn*64 + ni*8 + g;
            unsigned bH0 = BsH[tg*SW + cb], bH1 = BsH[(tg+4)*SW + cb];
            unsigned bL0 = BsL[tg*SW + cb], bL1 = BsL[(tg+4)*SW + cb];
            #pragma unroll
            for (int mi = 0; mi < 2; mi++) {
                mma_bf16(acc[mi][ni][0], acc[mi][ni][1], acc[mi][ni][2], acc[mi][ni][3],
                         afH[mi][0], afH[mi][1], afH[mi][2], afH[mi][3], bL0, bL1);
                mma_bf16(acc[mi][ni][0], acc[mi][ni][1], acc[mi][ni][2], acc[mi][ni][3],
                         afL[mi][0], afL[mi][1], afL[mi][2], afL[mi][3], bH0, bH1);
                mma_bf16(acc[mi][ni][0], acc[mi][ni][1], acc[mi][ni][2], acc[mi][ni][3],
                         afH[mi][0], afH[mi][1], afH[mi][2], afH[mi][3], bH0, bH1);
            }
        }
        __syncthreads();
    }

    #pragma unroll
    for (int mi = 0; mi < 2; mi++) {
        #pragma unroll
        for (int ni = 0; ni < 8; ni++) {
            size_t iG = (size_t)blockIdx.y*128 + wm*32 + mi*16 + g;
            size_t jG = (size_t)blockIdx.x*128 + wn*64 + ni*8 + tg*2;
            *reinterpret_cast<float2*>(P + ((size_t)bh*SEQ + iG)*SEQ + jG) =
                make_float2(acc[mi][ni][0]*ATT_SCALE, acc[mi][ni][1]*ATT_SCALE);
            *reinterpret_cast<float2*>(P + ((size_t)bh*SEQ + iG + 8)*SEQ + jG) =
                make_float2(acc[mi][ni][2]*ATT_SCALE, acc[mi][ni][3]*ATT_SCALE);
        }
    }
}

// -------- causal row softmax (in-place on P); zero-fills masked tail -------
__global__ __launch_bounds__(128)
void softmax_causal(float* __restrict__ P) {
    int i = blockIdx.x, bh = blockIdx.y, n = i + 1;
    float* row = P + ((size_t)bh*SEQ + i)*SEQ;
    int tid = threadIdx.x;
    __shared__ float red[128];
    float lm = -1e30f;
    for (int j = tid; j < n; j += 128) lm = fmaxf(lm, row[j]);
    red[tid] = lm; __syncthreads();
    for (int s = 64; s > 0; s >>= 1) { if (tid < s) red[tid] = fmaxf(red[tid], red[tid+s]); __syncthreads(); }
    float mx = red[0]; __syncthreads();
    float ls = 0.f;
    for (int j = tid; j < n; j += 128) { float e = __expf(row[j] - mx); row[j] = e; ls += e; }
    red[tid] = ls; __syncthreads();
    for (int s = 64; s > 0; s >>= 1) { if (tid < s) red[tid] += red[tid+s]; __syncthreads(); }
    float inv = 1.0f / red[0];
    for (int j = tid; j < n; j += 128) row[j] *= inv;
    for (int j = n + tid; j < SEQ; j += 128) row[j] = 0.f;
}

// -------- knn row softmax: local prefix + 32 memory logits -----------------
__global__ __launch_bounds__(128)
void softmax_knn(float* __restrict__ P, float* __restrict__ TV) {
    int i = blockIdx.x, bh = blockIdx.y, n = i + 1;
    float* row = P + ((size_t)bh*SEQ + i)*SEQ;
    float* tvp = TV + ((size_t)bh*SEQ + i)*TOPK;
    int tid = threadIdx.x;
    __shared__ float red[128];
    __shared__ float tvs[TOPK];
    float lm = -1e30f;
    for (int j = tid; j < n; j += 128) lm = fmaxf(lm, row[j]);
    if (tid < TOPK) lm = fmaxf(lm, tvp[tid]);
    red[tid] = lm; __syncthreads();
    for (int s = 64; s > 0; s >>= 1) { if (tid < s) red[tid] = fmaxf(red[tid], red[tid+s]); __syncthreads(); }
    float mx = red[0]; __syncthreads();
    float ls = 0.f;
    for (int j = tid; j < n; j += 128) { float e = __expf(row[j] - mx); row[j] = e; ls += e; }
    if (tid < TOPK) { float e = __expf(tvp[tid] - mx); tvs[tid] = e; ls += e; }
    red[tid] = ls; __syncthreads();
    for (int s = 64; s > 0; s >>= 1) { if (tid < s) red[tid] += red[tid+s]; __syncthreads(); }
    float inv = 1.0f / red[0];
    for (int j = tid; j < n; j += 128) row[j] *= inv;
    for (int j = n + tid; j < SEQ; j += 128) row[j] = 0.f;
    if (tid < TOPK) tvp[tid] = tvs[tid] * inv;
}

// -------- memory gather: O = sum_t a_mem[t] * MV[idx[t]] -------------------
__global__ __launch_bounds__(64)
void mem_gather(const float* __restrict__ MV, const float* __restrict__ TV,
                const int* __restrict__ TI, float* __restrict__ O) {
    int i = blockIdx.x, bh = blockIdx.y, b = bh >> 3, h = bh & 7;
    int tid = threadIdx.x;
    __shared__ float tv[TOPK];
    __shared__ int   ti[TOPK];
    if (tid < TOPK) {
        tv[tid] = TV[((size_t)bh*SEQ + i)*TOPK + tid];
        ti[tid] = TI[((size_t)bh*SEQ + i)*TOPK + tid];
    }
    __syncthreads();
    const float* mvb = MV + (size_t)b * MEMN * DHEAD;
    float acc = 0.f;
    #pragma unroll
    for (int t = 0; t < TOPK; t++)
        acc += tv[t] * mvb[(size_t)ti[t] * DHEAD + tid];
    O[(size_t)(b*SEQ + i)*DIM + h*DHEAD + tid] = acc;
}

// -------- AV GEMM: O(+)= P[bh] @ V[b,:,h,:]; 128x64 tile, K=SEQ ------------
#define SWB 72
__global__ __launch_bounds__(256)
void av_tc(const float* __restrict__ P, const float* __restrict__ Vm,
           float* __restrict__ O, int accum) {
    __shared__ unsigned AsH[8*SW], AsL[8*SW];
    __shared__ unsigned BsH[8*SWB], BsL[8*SWB];
    int tid = threadIdx.x, lane = tid & 31, warp = tid >> 5;
    int wm = warp & 3, wn = warp >> 2;
    int g = lane >> 2, tg = lane & 3;
    int by = blockIdx.x, bh = blockIdx.y, b = bh >> 3, h = bh & 7;

    int aRow = tid >> 1, aJ0 = (tid & 1) * 4;
    int kp = tid >> 5, col2 = (tid & 31) * 2;

    const float* Ab = P + ((size_t)bh*SEQ + by*128 + aRow)*SEQ + aJ0*2;
    const float* Bb = Vm + (size_t)(b*SEQ + kp*2)*DIM + h*DHEAD + col2;

    float acc[2][4][4];
    #pragma unroll
    for (int mi = 0; mi < 2; mi++)
        #pragma unroll
        for (int ni = 0; ni < 4; ni++)
            #pragma unroll
            for (int r = 0; r < 4; r++) acc[mi][ni][r] = 0.f;

    for (int k0 = 0; k0 < SEQ; k0 += 16) {
        float4 a0 = *reinterpret_cast<const float4*>(Ab + k0);
        float4 a1 = *reinterpret_cast<const float4*>(Ab + k0 + 4);
        float af8[8] = {a0.x,a0.y,a0.z,a0.w,a1.x,a1.y,a1.z,a1.w};
        #pragma unroll
        for (int jj = 0; jj < 4; jj++) {
            float x = af8[2*jj], y = af8[2*jj+1];
            float hx = bfhi(x), hy = bfhi(y);
            AsH[(aJ0+jj)*SW + aRow] = bfpack(hx, hy);
            AsL[(aJ0+jj)*SW + aRow] = bfpack(x - hx, y - hy);
        }
        float2 b0 = *reinterpret_cast<const float2*>(Bb + (size_t)k0*DIM);
        float2 b1 = *reinterpret_cast<const float2*>(Bb + (size_t)k0*DIM + DIM);
        {
            float hx = bfhi(b0.x), hy = bfhi(b1.x);
            BsH[kp*SWB + col2]   = bfpack(hx, hy);
            BsL[kp*SWB + col2]   = bfpack(b0.x - hx, b1.x - hy);
            float hx2 = bfhi(b0.y), hy2 = bfhi(b1.y);
            BsH[kp*SWB + col2+1] = bfpack(hx2, hy2);
            BsL[kp*SWB + col2+1] = bfpack(b0.y - hx2, b1.y - hy2);
        }
        __syncthreads();

        unsigned afH[2][4], afL[2][4];
        #pragma unroll
        for (int mi = 0; mi < 2; mi++) {
            int rb = wm*32 + mi*16 + g;
            afH[mi][0] = AsH[tg*SW + rb];       afL[mi][0] = AsL[tg*SW + rb];
            afH[mi][1] = AsH[tg*SW + rb+8];     afL[mi][1] = AsL[tg*SW + rb+8];
            afH[mi][2] = AsH[(tg+4)*SW + rb];   afL[mi][2] = AsL[(tg+4)*SW + rb];
            afH[mi][3] = AsH[(tg+4)*SW + rb+8]; afL[mi][3] = AsL[(tg+4)*SW + rb+8];
        }
        #pragma unroll
        for (int ni = 0; ni < 4; ni++) {
            int cb = wn*32 + ni*8 + g;
            unsigned bH0 = BsH[tg*SWB + cb], bH1 = BsH[(tg+4)*SWB + cb];
            unsigned bL0 = BsL[tg*SWB + cb], bL1 = BsL[(tg+4)*SWB + cb];
            #pragma unroll
            for (int mi = 0; mi < 2; mi++) {
                mma_bf16(acc[mi][ni][0], acc[mi][ni][1], acc[mi][ni][2], acc[mi][ni][3],
                         afH[mi][0], afH[mi][1], afH[mi][2], afH[mi][3], bL0, bL1);
                mma_bf16(acc[mi][ni][0], acc[mi][ni][1], acc[mi][ni][2], acc[mi][ni][3],
                         afL[mi][0], afL[mi][1], afL[mi][2], afL[mi][3], bH0, bH1);
                mma_bf16(acc[mi][ni][0], acc[mi][ni][1], acc[mi][ni][2], acc[mi][ni][3],
                         afH[mi][0], afH[mi][1], afH[mi][2], afH[mi][3], bH0, bH1);
            }
        }
        __syncthreads();
    }

    #pragma unroll
    for (int mi = 0; mi < 2; mi++) {
        #pragma unroll
        for (int ni = 0; ni < 4; ni++) {
            int row = by*128 + wm*32 + mi*16 + g;
            int col = wn*32 + ni*8 + tg*2;
            float* o0 = O + (size_t)(b*SEQ + row)*DIM + h*DHEAD + col;
            float* o1 = O + (size_t)(b*SEQ + row + 8)*DIM + h*DHEAD + col;
            float v0 = acc[mi][ni][0], v1 = acc[mi][ni][1];
            float v2 = acc[mi][ni][2], v3 = acc[mi][ni][3];
            if (accum) {
                float2 r0 = *reinterpret_cast<const float2*>(o0);
                float2 r1 = *reinterpret_cast<const float2*>(o1);
                v0 += r0.x; v1 += r0.y; v2 += r1.x; v3 += r1.y;
            }
            *reinterpret_cast<float2*>(o0) = make_float2(v0, v1);
            *reinterpret_cast<float2*>(o1) = make_float2(v2, v3);
        }
    }
}

// -------- top-32 per (bh,i) -------------------------------------------------
__global__ __launch_bounds__(256)
void topk_kernel(const float* __restrict__ S, float* __restrict__ TV,
                 int* __restrict__ TI) {
    int i = blockIdx.x, bh = blockIdx.y;
    const float* row = S + ((size_t)bh*SEQ + i)*MEMN;
    __shared__ float sv[MEMN];
    __shared__ float wv[8];
    __shared__ int   wi[8];
    __shared__ int wini;
    int tid = threadIdx.x;

    float lmax = -1e30f; int lidx = 0;
    #pragma unroll 4
    for (int j = 0; j < 16; j++) {
        int m = tid + 256*j;
        float v = row[m];
        sv[m] = v;
        if (v > lmax) { lmax = v; lidx = m; }
    }
    for (int t = 0; t < TOPK; t++) {
        float v = lmax; int idx = lidx;
        #pragma unroll
        for (int o = 16; o > 0; o >>= 1) {
            float ov = __shfl_xor_sync(0xffffffffu, v, o);
            int   oi = __shfl_xor_sync(0xffffffffu, idx, o);
            if (ov > v) { v = ov; idx = oi; }
        }
        if ((tid & 31) == 0) { wv[tid>>5] = v; wi[tid>>5] = idx; }
        __syncthreads();
        if (tid < 32) {
            float v2 = (tid < 8) ? wv[tid] : -1e30f;
            int   i2 = (tid < 8) ? wi[tid] : 0;
            #pragma unroll
            for (int o = 4; o > 0; o >>= 1) {
                float ov = __shfl_xor_sync(0xffffffffu, v2, o);
                int   oi = __shfl_xor_sync(0xffffffffu, i2, o);
                if (ov > v2) { v2 = ov; i2 = oi; }
            }
            if (tid == 0) {
                wini = i2;
                TV[((size_t)bh*SEQ + i)*TOPK + t] = v2;
                TI[((size_t)bh*SEQ + i)*TOPK + t] = i2;
            }
        }
        __syncthreads();
        int widx = wini;
        if ((widx & 255) == tid) {
            sv[widx] = -1e30f;
            lmax = -1e30f; lidx = 0;
            #pragma unroll 4
            for (int j = 0; j < 16; j++) {
                int m = tid + 256*j;
                float vv = sv[m];
                if (vv > lmax) { lmax = vv; lidx = m; }
            }
        }
    }
}

// ---------------- host orchestration --------------------------------------
extern "C" void kernel_launch(void* const* d_in, const int* in_sizes, int n_in,
                              void* d_out, int out_size) {
    const float* x     = (const float*)d_in[0];
    const float* Wq    = (const float*)d_in[1];
    const float* Wk    = (const float*)d_in[2];
    const float* Wv    = (const float*)d_in[3];
    const float* Wo    = (const float*)d_in[4];
    const float* ln1s  = (const float*)d_in[5];
    const float* ln1b  = (const float*)d_in[6];
    const float* ln2s  = (const float*)d_in[7];
    const float* ln2b  = (const float*)d_in[8];
    const float* W1    = (const float*)d_in[9];
    const float* W2    = (const float*)d_in[10];
    const float* lnfs  = (const float*)d_in[11];
    const float* lnfb  = (const float*)d_in[12];
    const float* mem_k = (const float*)d_in[13];
    const float* mem_v = (const float*)d_in[14];

    float *X, *H, *Q, *K, *V, *AO, *FFb, *S, *P, *TV;
    int *TI;
    cudaGetSymbolAddress((void**)&X,  g_X);
    cudaGetSymbolAddress((void**)&H,  g_H);
    cudaGetSymbolAddress((void**)&Q,  g_Q);
    cudaGetSymbolAddress((void**)&K,  g_K);
    cudaGetSymbolAddress((void**)&V,  g_V);
    cudaGetSymbolAddress((void**)&AO, g_AO);
    cudaGetSymbolAddress((void**)&FFb, g_FF);
    cudaGetSymbolAddress((void**)&S,  g_S);
    cudaGetSymbolAddress((void**)&P,  g_P);
    cudaGetSymbolAddress((void**)&TV, g_TV);
    cudaGetSymbolAddress((void**)&TI, g_TI);

    cudaMemcpyAsync(X, x, sizeof(float) * MROWS * DIM, cudaMemcpyDeviceToDevice);

    dim3 gD(DIM/128, MROWS/128);         // 4 x 32
    dim3 gQKV(DIM/128, MROWS/128, 3);    // fused QKV
    dim3 gF(FFDIM/128, MROWS/128);       // 16 x 32
    dim3 gSim(MEMN/128, SEQ/128, NBH);
    dim3 gLoc(SEQ/128, SEQ/128, NBH);    // 4 x 4 x 64
    dim3 gRow(SEQ, NBH);                 // 512 x 64
    dim3 gAV(MROWS/128 / BATCH, NBH);    // 4 x 64

    int mi = 0;
    for (int l = 0; l < DEPTH; l++) {
        ln_kernel<<<MROWS, 128>>>(X, ln1s + l*DIM, ln1b + l*DIM, H);
        gemm_qkv<<<gQKV, 256>>>(H, Wq + (size_t)l*DIM*DIM, Wk + (size_t)l*DIM*DIM,
                                Wv + (size_t)l*DIM*DIM, Q, K, V);
        if (l == 3 || l == 4) {
            const float* MK = mem_k + (size_t)mi * BATCH * MEMN * DHEAD;
            const float* MV = mem_v + (size_t)mi * BATCH * MEMN * DHEAD;
            knn_sim_tc<<<gSim, 256>>>(Q, MK, S);
            topk_kernel<<<gRow, 256>>>(S, TV, TI);
            sim_local_tc<<<gLoc, 256>>>(Q, K, P);
            softmax_knn<<<gRow, 128>>>(P, TV);
            mem_gather<<<gRow, 64>>>(MV, TV, TI, AO);
            av_tc<<<gAV, 256>>>(P, V, AO, 1);
            mi++;
        } else {
            sim_local_tc<<<gLoc, 256>>>(Q, K, P);
            softmax_causal<<<gRow, 128>>>(P);
            av_tc<<<gAV, 256>>>(P, V, AO, 0);
        }
        gemm_tc<<<gD, 256>>>(AO, Wo + (size_t)l*DIM*DIM, X, X, DIM, DIM, 0);
        ln_kernel<<<MROWS, 128>>>(X, ln2s + l*DIM, ln2b + l*DIM, H);
        gemm_tc<<<gF, 256>>>(H, W1 + (size_t)l*DIM*FFDIM, nullptr, FFb, FFDIM, DIM, 1);
        gemm_tc<<<gD, 256>>>(FFb, W2 + (size_t)l*FFDIM*DIM, X, X, DIM, FFDIM, 0);
    }
    ln_kernel<<<MROWS, 128>>>(X, lnfs, lnfb, (float*)d_out);
}

// round 6
// speedup vs baseline: 3.6342x; 1.0096x over previous
#include <cuda_runtime.h>
#include <cuda_bf16.h>
#include <math.h>

#define BATCH   8
#define SEQ     512
#define DIM     512
#define NHEADS  8
#define DHEAD   64
#define MEMN    4096
#define TOPK    32
#define FFDIM   2048
#define DEPTH   6
#define MROWS   (BATCH*SEQ)    /* 4096 */
#define NBH     (BATCH*NHEADS) /* 64 */
#define ATT_SCALE 0.125f
#define PQ      (DIM*DIM/2)    /* 131072 pair-words per DxD weight layer */
#define PF      (DIM*FFDIM/2)  /* 524288 pair-words per FF weight layer */

// ---------------- scratch (device globals; no allocation allowed) ----------
__device__ float g_X [MROWS*DIM];
__device__ float g_H [MROWS*DIM];
__device__ float g_Q [MROWS*DIM];
__device__ float g_K [MROWS*DIM];
__device__ float g_V [MROWS*DIM];
__device__ float g_AO[MROWS*DIM];
__device__ float g_FF[MROWS*FFDIM];
__device__ float g_S [(size_t)NBH*SEQ*MEMN];
__device__ float g_P [(size_t)NBH*SEQ*SEQ];
__device__ float g_TV[(size_t)NBH*SEQ*TOPK];
__device__ int   g_TI[(size_t)NBH*SEQ*TOPK];
// pre-split weights: [Wq(6) Wk(6) Wv(6) Wo(6) W1(6) W2(6)] as packed bf16 k-pair words
#define WTOTAL (24*PQ + 12*PF)
__device__ unsigned g_WH[WTOTAL];
__device__ unsigned g_WL[WTOTAL];

__device__ __forceinline__ float warp_sum(float v) {
    #pragma unroll
    for (int o = 16; o > 0; o >>= 1) v += __shfl_xor_sync(0xffffffffu, v, o);
    return v;
}
__device__ __forceinline__ float gelu_f(float v) {
    float c = v + 0.044715f * v * v * v;
    return 0.5f * v * (1.0f + tanhf(0.7978845608028654f * c));
}
__device__ __forceinline__ unsigned bfpack(float x, float y) {
    __nv_bfloat162 p = __floats2bfloat162_rn(x, y);
    return *reinterpret_cast<unsigned*>(&p);
}
__device__ __forceinline__ float bfhi(float x) {
    return __bfloat162float(__float2bfloat16(x));
}
__device__ __forceinline__ void mma_bf16(float& d0, float& d1, float& d2, float& d3,
                                         unsigned a0, unsigned a1, unsigned a2, unsigned a3,
                                         unsigned b0, unsigned b1) {
    asm volatile(
        "mma.sync.aligned.m16n8k16.row.col.f32.bf16.bf16.f32 "
        "{%0,%1,%2,%3}, {%4,%5,%6,%7}, {%8,%9}, {%0,%1,%2,%3};\n"
        : "+f"(d0), "+f"(d1), "+f"(d2), "+f"(d3)
        : "r"(a0), "r"(a1), "r"(a2), "r"(a3), "r"(b0), "r"(b1));
}

// ---- weight pre-split: W[K,N] fp32 -> packed (k,k+1) bf16 hi/lo words -----
__global__ void split_w(const float* __restrict__ W, unsigned* __restrict__ WH,
                        unsigned* __restrict__ WL, int KN2, int N) {
    int l = blockIdx.y;
    int idx = blockIdx.x * 256 + threadIdx.x;
    if (idx >= KN2) return;
    int kpr = idx / N, c = idx - kpr * N;
    const float* Wl = W + (size_t)l * 2 * KN2;
    float x = Wl[(size_t)(2*kpr) * N + c];
    float y = Wl[(size_t)(2*kpr+1) * N + c];
    float hx = bfhi(x), hy = bfhi(y);
    WH[(size_t)l*KN2 + idx] = bfpack(hx, hy);
    WL[(size_t)l*KN2 + idx] = bfpack(x - hx, y - hy);
}

// ---------------- LayerNorm -------------------------------------------------
__global__ void ln_kernel(const float* __restrict__ x,
                          const float* __restrict__ sc,
                          const float* __restrict__ bi,
                          float* __restrict__ out) {
    int row = blockIdx.x;
    int tid = threadIdx.x;
    const float4* xr = reinterpret_cast<const float4*>(x + (size_t)row * DIM);
    float4 v = xr[tid];
    float s  = v.x + v.y + v.z + v.w;
    float sq = v.x*v.x + v.y*v.y + v.z*v.z + v.w*v.w;
    __shared__ float ss[4], sqs[4];
    s  = warp_sum(s);
    sq = warp_sum(sq);
    int w = tid >> 5, lane = tid & 31;
    if (lane == 0) { ss[w] = s; sqs[w] = sq; }
    __syncthreads();
    float tot  = ss[0] + ss[1] + ss[2] + ss[3];
    float totq = sqs[0] + sqs[1] + sqs[2] + sqs[3];
    float mean = tot * (1.0f / DIM);
    float var  = totq * (1.0f / DIM) - mean * mean;
    float rstd = rsqrtf(var + 1e-5f);
    float4 sv = reinterpret_cast<const float4*>(sc)[tid];
    float4 bv = reinterpret_cast<const float4*>(bi)[tid];
    float4 o;
    o.x = (v.x - mean) * rstd * sv.x + bv.x;
    o.y = (v.y - mean) * rstd * sv.y + bv.y;
    o.z = (v.z - mean) * rstd * sv.z + bv.z;
    o.w = (v.w - mean) * rstd * sv.w + bv.w;
    reinterpret_cast<float4*>(out + (size_t)row * DIM)[tid] = o;
}

// ---- pipelined bf16-split GEMM body: C = act(A@B (+R)); B pre-split -------
#define SW 136
__device__ __forceinline__ void gemm_body(
    const float* __restrict__ A, const unsigned* __restrict__ BH,
    const unsigned* __restrict__ BL,
    const float* __restrict__ R, float* __restrict__ C,
    int N, int K, int act, int bx, int by)
{
    __shared__ unsigned AsH[2][8*SW], AsL[2][8*SW];
    __shared__ unsigned BsH[2][8*SW], BsL[2][8*SW];
    int tid = threadIdx.x, lane = tid & 31, warp = tid >> 5;
    int wm = warp & 3, wn = warp >> 2;
    int g = lane >> 2, tg = lane & 3;

    int aRow = tid >> 1, aJ0 = (tid & 1) * 4;
    int kp = tid >> 5, col4 = (tid & 31) * 4;

    const float*    Ab  = A  + (size_t)(by * 128 + aRow) * K + aJ0 * 2;
    const unsigned* BHb = BH + (size_t)kp * N + bx * 128 + col4;
    const unsigned* BLb = BL + (size_t)kp * N + bx * 128 + col4;

    float acc[2][8][4];
    #pragma unroll
    for (int mi = 0; mi < 2; mi++)
        #pragma unroll
        for (int ni = 0; ni < 8; ni++)
            #pragma unroll
            for (int r = 0; r < 4; r++) acc[mi][ni][r] = 0.f;

    // prefetch stage 0
    float4 a0 = *reinterpret_cast<const float4*>(Ab);
    float4 a1 = *reinterpret_cast<const float4*>(Ab + 4);
    uint4  bh = *reinterpret_cast<const uint4*>(BHb);
    uint4  bl = *reinterpret_cast<const uint4*>(BLb);

    int buf = 0;
    for (int k0 = 0; k0 < K; k0 += 16) {
        // STS current stage
        {
            float af8[8] = {a0.x,a0.y,a0.z,a0.w,a1.x,a1.y,a1.z,a1.w};
            #pragma unroll
            for (int jj = 0; jj < 4; jj++) {
                float x = af8[2*jj], y = af8[2*jj+1];
                float hx = bfhi(x), hy = bfhi(y);
                AsH[buf][(aJ0+jj)*SW + aRow] = bfpack(hx, hy);
                AsL[buf][(aJ0+jj)*SW + aRow] = bfpack(x - hx, y - hy);
            }
            *reinterpret_cast<uint4*>(&BsH[buf][kp*SW + col4]) = bh;
            *reinterpret_cast<uint4*>(&BsL[buf][kp*SW + col4]) = bl;
        }
        __syncthreads();
        // prefetch next stage
        if (k0 + 16 < K) {
            a0 = *reinterpret_cast<const float4*>(Ab + k0 + 16);
            a1 = *reinterpret_cast<const float4*>(Ab + k0 + 20);
            bh = *reinterpret_cast<const uint4*>(BHb + (size_t)(k0/2 + 8) * N);
            bl = *reinterpret_cast<const uint4*>(BLb + (size_t)(k0/2 + 8) * N);
        }
        // compute current stage
        const unsigned* asH = AsH[buf]; const unsigned* asL = AsL[buf];
        const unsigned* bsH = BsH[buf]; const unsigned* bsL = BsL[buf];
        unsigned afH[2][4], afL[2][4];
        #pragma unroll
        for (int mi = 0; mi < 2; mi++) {
            int rb = wm*32 + mi*16 + g;
            afH[mi][0] = asH[tg*SW + rb];       afL[mi][0] = asL[tg*SW + rb];
            afH[mi][1] = asH[tg*SW + rb+8];     afL[mi][1] = asL[tg*SW + rb+8];
            afH[mi][2] = asH[(tg+4)*SW + rb];   afL[mi][2] = asL[(tg+4)*SW + rb];
            afH[mi][3] = asH[(tg+4)*SW + rb+8]; afL[mi][3] = asL[(tg+4)*SW + rb+8];
        }
        #pragma unroll
        for (int ni = 0; ni < 8; ni++) {
            int cb = wn*64 + ni*8 + g;
            unsigned bH0 = bsH[tg*SW + cb], bH1 = bsH[(tg+4)*SW + cb];
            unsigned bL0 = bsL[tg*SW + cb], bL1 = bsL[(tg+4)*SW + cb];
            #pragma unroll
            for (int mi = 0; mi < 2; mi++) {
                mma_bf16(acc[mi][ni][0], acc[mi][ni][1], acc[mi][ni][2], acc[mi][ni][3],
                         afH[mi][0], afH[mi][1], afH[mi][2], afH[mi][3], bL0, bL1);
                mma_bf16(acc[mi][ni][0], acc[mi][ni][1], acc[mi][ni][2], acc[mi][ni][3],
                         afL[mi][0], afL[mi][1], afL[mi][2], afL[mi][3], bH0, bH1);
                mma_bf16(acc[mi][ni][0], acc[mi][ni][1], acc[mi][ni][2], acc[mi][ni][3],
                         afH[mi][0], afH[mi][1], afH[mi][2], afH[mi][3], bH0, bH1);
            }
        }
        buf ^= 1;
    }

    #pragma unroll
    for (int mi = 0; mi < 2; mi++) {
        #pragma unroll
        for (int ni = 0; ni < 8; ni++) {
            size_t row = (size_t)by*128 + wm*32 + mi*16 + g;
            size_t col = (size_t)bx*128 + wn*64 + ni*8 + tg*2;
            float v0 = acc[mi][ni][0], v1 = acc[mi][ni][1];
            float v2 = acc[mi][ni][2], v3 = acc[mi][ni][3];
            if (act) { v0 = gelu_f(v0); v1 = gelu_f(v1); v2 = gelu_f(v2); v3 = gelu_f(v3); }
            if (R) {
                float2 r0 = *reinterpret_cast<const float2*>(R + row*N + col);
                float2 r1 = *reinterpret_cast<const float2*>(R + (row+8)*N + col);
                v0 += r0.x; v1 += r0.y; v2 += r1.x; v3 += r1.y;
            }
            *reinterpret_cast<float2*>(C + row*N + col)     = make_float2(v0, v1);
            *reinterpret_cast<float2*>(C + (row+8)*N + col) = make_float2(v2, v3);
        }
    }
}

__global__ __launch_bounds__(256)
void gemm_tc(const float* __restrict__ A, const unsigned* __restrict__ BH,
             const unsigned* __restrict__ BL,
             const float* __restrict__ R, float* __restrict__ C,
             int N, int K, int act) {
    gemm_body(A, BH, BL, R, C, N, K, act, blockIdx.x, blockIdx.y);
}

// fused QKV: blockIdx.z selects weight/output
__global__ __launch_bounds__(256)
void gemm_qkv(const float* __restrict__ H,
              const unsigned* __restrict__ WH, const unsigned* __restrict__ WL,
              int lofsQ, int lofsK, int lofsV,
              float* __restrict__ Q, float* __restrict__ K, float* __restrict__ V) {
    int ofs = (blockIdx.z == 0) ? lofsQ : (blockIdx.z == 1) ? lofsK : lofsV;
    float* C = (blockIdx.z == 0) ? Q : (blockIdx.z == 1) ? K : V;
    gemm_body(H, WH + ofs, WL + ofs, nullptr, C, DIM, DIM, 0, blockIdx.x, blockIdx.y);
}

// -------- bf16-split KNN sim (NT): S[bh,i,m] = scale * q . mk --------------
__global__ __launch_bounds__(256)
void knn_sim_tc(const float* __restrict__ Q, const float* __restrict__ MK,
                float* __restrict__ S) {
    __shared__ unsigned AsH[8*SW], AsL[8*SW];
    __shared__ unsigned BsH[8*SW], BsL[8*SW];
    int tid = threadIdx.x, lane = tid & 31, warp = tid >> 5;
    int wm = warp & 3, wn = warp >> 2;
    int g = lane >> 2, tg = lane & 3;
    int bh = blockIdx.z, b = bh >> 3, h = bh & 7;

    int lRow = tid >> 1, lJ0 = (tid & 1) * 4;
    const float* Qb = Q + (size_t)(b*SEQ + blockIdx.y*128 + lRow) * DIM + h*DHEAD + lJ0*2;
    const float* Mb = MK + (size_t)(b*MEMN + blockIdx.x*128 + lRow) * DHEAD + lJ0*2;

    float acc[2][8][4];
    #pragma unroll
    for (int mi = 0; mi < 2; mi++)
        #pragma unroll
        for (int ni = 0; ni < 8; ni++)
            #pragma unroll
            for (int r = 0; r < 4; r++) acc[mi][ni][r] = 0.f;

    for (int k0 = 0; k0 < DHEAD; k0 += 16) {
        float4 a0 = *reinterpret_cast<const float4*>(Qb + k0);
        float4 a1 = *reinterpret_cast<const float4*>(Qb + k0 + 4);
        float af8[8] = {a0.x,a0.y,a0.z,a0.w,a1.x,a1.y,a1.z,a1.w};
        float4 b0 = *reinterpret_cast<const float4*>(Mb + k0);
        float4 b1 = *reinterpret_cast<const float4*>(Mb + k0 + 4);
        float bf8[8] = {b0.x,b0.y,b0.z,b0.w,b1.x,b1.y,b1.z,b1.w};
        #pragma unroll
        for (int jj = 0; jj < 4; jj++) {
            float x = af8[2*jj], y = af8[2*jj+1];
            float hx = bfhi(x), hy = bfhi(y);
            AsH[(lJ0+jj)*SW + lRow] = bfpack(hx, hy);
            AsL[(lJ0+jj)*SW + lRow] = bfpack(x - hx, y - hy);
            float u = bf8[2*jj], v = bf8[2*jj+1];
            float hu = bfhi(u), hv = bfhi(v);
            BsH[(lJ0+jj)*SW + lRow] = bfpack(hu, hv);
            BsL[(lJ0+jj)*SW + lRow] = bfpack(u - hu, v - hv);
        }
        __syncthreads();
        unsigned afH[2][4], afL[2][4];
        #pragma unroll
        for (int mi = 0; mi < 2; mi++) {
            int rb = wm*32 + mi*16 + g;
            afH[mi][0] = AsH[tg*SW + rb];       afL[mi][0] = AsL[tg*SW + rb];
            afH[mi][1] = AsH[tg*SW + rb+8];     afL[mi][1] = AsL[tg*SW + rb+8];
            afH[mi][2] = AsH[(tg+4)*SW + rb];   afL[mi][2] = AsL[(tg+4)*SW + rb];
            afH[mi][3] = AsH[(tg+4)*SW + rb+8]; afL[mi][3] = AsL[(tg+4)*SW + rb+8];
        }
        #pragma unroll
        for (int ni = 0; ni < 8; ni++) {
            int cb = wn*64 + ni*8 + g;
            unsigned bH0 = BsH[tg*SW + cb], bH1 = BsH[(tg+4)*SW + cb];
            unsigned bL0 = BsL[tg*SW + cb], bL1 = BsL[(tg+4)*SW + cb];
            #pragma unroll
            for (int mi = 0; mi < 2; mi++) {
                mma_bf16(acc[mi][ni][0], acc[mi][ni][1], acc[mi][ni][2], acc[mi][ni][3],
                         afH[mi][0], afH[mi][1], afH[mi][2], afH[mi][3], bL0, bL1);
                mma_bf16(acc[mi][ni][0], acc[mi][ni][1], acc[mi][ni][2], acc[mi][ni][3],
                         afL[mi][0], afL[mi][1], afL[mi][2], afL[mi][3], bH0, bH1);
                mma_bf16(acc[mi][ni][0], acc[mi][ni][1], acc[mi][ni][2], acc[mi][ni][3],
                         afH[mi][0], afH[mi][1], afH[mi][2], afH[mi][3], bH0, bH1);
            }
        }
        __syncthreads();
    }

    #pragma unroll
    for (int mi = 0; mi < 2; mi++) {
        #pragma unroll
        for (int ni = 0; ni < 8; ni++) {
            size_t iG = (size_t)blockIdx.y*128 + wm*32 + mi*16 + g;
            size_t mG = (size_t)blockIdx.x*128 + wn*64 + ni*8 + tg*2;
            *reinterpret_cast<float2*>(S + ((size_t)bh*SEQ + iG)*MEMN + mG) =
                make_float2(acc[mi][ni][0]*ATT_SCALE, acc[mi][ni][1]*ATT_SCALE);
            *reinterpret_cast<float2*>(S + ((size_t)bh*SEQ + iG + 8)*MEMN + mG) =
                make_float2(acc[mi][ni][2]*ATT_SCALE, acc[mi][ni][3]*ATT_SCALE);
        }
    }
}

// -------- bf16-split local sim (NT): P[bh,i,j] = scale * q . k -------------
__global__ __launch_bounds__(256)
void sim_local_tc(const float* __restrict__ Q, const float* __restrict__ Km,
                  float* __restrict__ P) {
    if (blockIdx.x > blockIdx.y) return;
    __shared__ unsigned AsH[8*SW], AsL[8*SW];
    __shared__ unsigned BsH[8*SW], BsL[8*SW];
    int tid = threadIdx.x, lane = tid & 31, warp = tid >> 5;
    int wm = warp & 3, wn = warp >> 2;
    int g = lane >> 2, tg = lane & 3;
    int bh = blockIdx.z, b = bh >> 3, h = bh & 7;

    int lRow = tid >> 1, lJ0 = (tid & 1) * 4;
    const float* Qb = Q + (size_t)(b*SEQ + blockIdx.y*128 + lRow) * DIM + h*DHEAD + lJ0*2;
    const float* Mb = Km + (size_t)(b*SEQ + blockIdx.x*128 + lRow) * DIM + h*DHEAD + lJ0*2;

    float acc[2][8][4];
    #pragma unroll
    for (int mi = 0; mi < 2; mi++)
        #pragma unroll
        for (int ni = 0; ni < 8; ni++)
            #pragma unroll
            for (int r = 0; r < 4; r++) acc[mi][ni][r] = 0.f;

    for (int k0 = 0; k0 < DHEAD; k0 += 16) {
        float4 a0 = *reinterpret_cast<const float4*>(Qb + k0);
        float4 a1 = *reinterpret_cast<const float4*>(Qb + k0 + 4);
        float af8[8] = {a0.x,a0.y,a0.z,a0.w,a1.x,a1.y,a1.z,a1.w};
        float4 b0 = *reinterpret_cast<const float4*>(Mb + k0);
        float4 b1 = *reinterpret_cast<const float4*>(Mb + k0 + 4);
        float bf8[8] = {b0.x,b0.y,b0.z,b0.w,b1.x,b1.y,b1.z,b1.w};
        #pragma unroll
        for (int jj = 0; jj < 4; jj++) {
            float x = af8[2*jj], y = af8[2*jj+1];
            float hx = bfhi(x), hy = bfhi(y);
            AsH[(lJ0+jj)*SW + lRow] = bfpack(hx, hy);
            AsL[(lJ0+jj)*SW + lRow] = bfpack(x - hx, y - hy);
            float u = bf8[2*jj], v = bf8[2*jj+1];
            float hu = bfhi(u), hv = bfhi(v);
            BsH[(lJ0+jj)*SW + lRow] = bfpack(hu, hv);
            BsL[(lJ0+jj)*SW + lRow] = bfpack(u - hu, v - hv);
        }
        __syncthreads();
        unsigned afH[2][4], afL[2][4];
        #pragma unroll
        for (int mi = 0; mi < 2; mi++) {
            int rb = wm*32 + mi*16 + g;
            afH[mi][0] = AsH[tg*SW + rb];       afL[mi][0] = AsL[tg*SW + rb];
            afH[mi][1] = AsH[tg*SW + rb+8];     afL[mi][1] = AsL[tg*SW + rb+8];
            afH[mi][2] = AsH[(tg+4)*SW + rb];   afL[mi][2] = AsL[(tg+4)*SW + rb];
            afH[mi][3] = AsH[(tg+4)*SW + rb+8]; afL[mi][3] = AsL[(tg+4)*SW + rb+8];
        }
        #pragma unroll
        for (int ni = 0; ni < 8; ni++) {
            int cb = wn*64 + ni*8 + g;
            unsigned bH0 = BsH[tg*SW + cb], bH1 = BsH[(tg+4)*SW + cb];
            unsigned bL0 = BsL[tg*SW + cb], bL1 = BsL[(tg+4)*SW + cb];
            #pragma unroll
            for (int mi = 0; mi < 2; mi++) {
                mma_bf16(acc[mi][ni][0], acc[mi][ni][1], acc[mi][ni][2], acc[mi][ni][3],
                         afH[mi][0], afH[mi][1], afH[mi][2], afH[mi][3], bL0, bL1);
                mma_bf16(acc[mi][ni][0], acc[mi][ni][1], acc[mi][ni][2], acc[mi][ni][3],
                         afL[mi][0], afL[mi][1], afL[mi][2], afL[mi][3], bH0, bH1);
                mma_bf16(acc[mi][ni][0], acc[mi][ni][1], acc[mi][ni][2], acc[mi][ni][3],
                         afH[mi][0], afH[mi][1], afH[mi][2], afH[mi][3], bH0, bH1);
            }
        }
        __syncthreads();
    }

    #pragma unroll
    for (int mi = 0; mi < 2; mi++) {
        #pragma unroll
        for (int ni = 0; ni < 8; ni++) {
            size_t iG = (size_t)blockIdx.y*128 + wm*32 + mi*16 + g;
            size_t jG = (size_t)blockIdx.x*128 + wn*64 + ni*8 + tg*2;
            *reinterpret_cast<float2*>(P + ((size_t)bh*SEQ + iG)*SEQ + jG) =
                make_float2(acc[mi][ni][0]*ATT_SCALE, acc[mi][ni][1]*ATT_SCALE);
            *reinterpret_cast<float2*>(P + ((size_t)bh*SEQ + iG + 8)*SEQ + jG) =
                make_float2(acc[mi][ni][2]*ATT_SCALE, acc[mi][ni][3]*ATT_SCALE);
        }
    }
}

// -------- causal row softmax (in-place on P); zero-fills masked tail -------
__global__ __launch_bounds__(128)
void softmax_causal(float* __restrict__ P) {
    int i = blockIdx.x, bh = blockIdx.y, n = i + 1;
    float* row = P + ((size_t)bh*SEQ + i)*SEQ;
    int tid = threadIdx.x;
    __shared__ float red[128];
    float lm = -1e30f;
    for (int j = tid; j < n; j += 128) lm = fmaxf(lm, row[j]);
    red[tid] = lm; __syncthreads();
    for (int s = 64; s > 0; s >>= 1) { if (tid < s) red[tid] = fmaxf(red[tid], red[tid+s]); __syncthreads(); }
    float mx = red[0]; __syncthreads();
    float ls = 0.f;
    for (int j = tid; j < n; j += 128) { float e = __expf(row[j] - mx); row[j] = e; ls += e; }
    red[tid] = ls; __syncthreads();
    for (int s = 64; s > 0; s >>= 1) { if (tid < s) red[tid] += red[tid+s]; __syncthreads(); }
    float inv = 1.0f / red[0];
    for (int j = tid; j < n; j += 128) row[j] *= inv;
    for (int j = n + tid; j < SEQ; j += 128) row[j] = 0.f;
}

// -------- knn row softmax: local prefix + 32 memory logits -----------------
__global__ __launch_bounds__(128)
void softmax_knn(float* __restrict__ P, float* __restrict__ TV) {
    int i = blockIdx.x, bh = blockIdx.y, n = i + 1;
    float* row = P + ((size_t)bh*SEQ + i)*SEQ;
    float* tvp = TV + ((size_t)bh*SEQ + i)*TOPK;
    int tid = threadIdx.x;
    __shared__ float red[128];
    __shared__ float tvs[TOPK];
    float lm = -1e30f;
    for (int j = tid; j < n; j += 128) lm = fmaxf(lm, row[j]);
    if (tid < TOPK) lm = fmaxf(lm, tvp[tid]);
    red[tid] = lm; __syncthreads();
    for (int s = 64; s > 0; s >>= 1) { if (tid < s) red[tid] = fmaxf(red[tid], red[tid+s]); __syncthreads(); }
    float mx = red[0]; __syncthreads();
    float ls = 0.f;
    for (int j = tid; j < n; j += 128) { float e = __expf(row[j] - mx); row[j] = e; ls += e; }
    if (tid < TOPK) { float e = __expf(tvp[tid] - mx); tvs[tid] = e; ls += e; }
    red[tid] = ls; __syncthreads();
    for (int s = 64; s > 0; s >>= 1) { if (tid < s) red[tid] += red[tid+s]; __syncthreads(); }
    float inv = 1.0f / red[0];
    for (int j = tid; j < n; j += 128) row[j] *= inv;
    for (int j = n + tid; j < SEQ; j += 128) row[j] = 0.f;
    if (tid < TOPK) tvp[tid] = tvs[tid] * inv;
}

// -------- memory gather: O = sum_t a_mem[t] * MV[idx[t]] -------------------
__global__ __launch_bounds__(64)
void mem_gather(const float* __restrict__ MV, const float* __restrict__ TV,
                const int* __restrict__ TI, float* __restrict__ O) {
    int i = blockIdx.x, bh = blockIdx.y, b = bh >> 3, h = bh & 7;
    int tid = threadIdx.x;
    __shared__ float tv[TOPK];
    __shared__ int   ti[TOPK];
    if (tid < TOPK) {
        tv[tid] = TV[((size_t)bh*SEQ + i)*TOPK + tid];
        ti[tid] = TI[((size_t)bh*SEQ + i)*TOPK + tid];
    }
    __syncthreads();
    const float* mvb = MV + (size_t)b * MEMN * DHEAD;
    float acc = 0.f;
    #pragma unroll
    for (int t = 0; t < TOPK; t++)
        acc += tv[t] * mvb[(size_t)ti[t] * DHEAD + tid];
    O[(size_t)(b*SEQ + i)*DIM + h*DHEAD + tid] = acc;
}

// -------- AV GEMM: O(+)= P[bh] @ V[b,:,h,:]; 128x64 tile, K=SEQ ------------
#define SWB 72
__global__ __launch_bounds__(256)
void av_tc(const float* __restrict__ P, const float* __restrict__ Vm,
           float* __restrict__ O, int accum) {
    __shared__ unsigned AsH[8*SW], AsL[8*SW];
    __shared__ unsigned BsH[8*SWB], BsL[8*SWB];
    int tid = threadIdx.x, lane = tid & 31, warp = tid >> 5;
    int wm = warp & 3, wn = warp >> 2;
    int g = lane >> 2, tg = lane & 3;
    int by = blockIdx.x, bh = blockIdx.y, b = bh >> 3, h = bh & 7;

    int aRow = tid >> 1, aJ0 = (tid & 1) * 4;
    int kp = tid >> 5, col2 = (tid & 31) * 2;

    const float* Ab = P + ((size_t)bh*SEQ + by*128 + aRow)*SEQ + aJ0*2;
    const float* Bb = Vm + (size_t)(b*SEQ + kp*2)*DIM + h*DHEAD + col2;

    float acc[2][4][4];
    #pragma unroll
    for (int mi = 0; mi < 2; mi++)
        #pragma unroll
        for (int ni = 0; ni < 4; ni++)
            #pragma unroll
            for (int r = 0; r < 4; r++) acc[mi][ni][r] = 0.f;

    for (int k0 = 0; k0 < SEQ; k0 += 16) {
        float4 a0 = *reinterpret_cast<const float4*>(Ab + k0);
        float4 a1 = *reinterpret_cast<const float4*>(Ab + k0 + 4);
        float af8[8] = {a0.x,a0.y,a0.z,a0.w,a1.x,a1.y,a1.z,a1.w};
        #pragma unroll
        for (int jj = 0; jj < 4; jj++) {
            float x = af8[2*jj], y = af8[2*jj+1];
            float hx = bfhi(x), hy = bfhi(y);
            AsH[(aJ0+jj)*SW + aRow] = bfpack(hx, hy);
            AsL[(aJ0+jj)*SW + aRow] = bfpack(x - hx, y - hy);
        }
        float2 b0 = *reinterpret_cast<const float2*>(Bb + (size_t)k0*DIM);
        float2 b1 = *reinterpret_cast<const float2*>(Bb + (size_t)k0*DIM + DIM);
        {
            float hx = bfhi(b0.x), hy = bfhi(b1.x);
            BsH[kp*SWB + col2]   = bfpack(hx, hy);
            BsL[kp*SWB + col2]   = bfpack(b0.x - hx, b1.x - hy);
            float hx2 = bfhi(b0.y), hy2 = bfhi(b1.y);
            BsH[kp*SWB + col2+1] = bfpack(hx2, hy2);
            BsL[kp*SWB + col2+1] = bfpack(b0.y - hx2, b1.y - hy2);
        }
        __syncthreads();

        unsigned afH[2][4], afL[2][4];
        #pragma unroll
        for (int mi = 0; mi < 2; mi++) {
            int rb = wm*32 + mi*16 + g;
            afH[mi][0] = AsH[tg*SW + rb];       afL[mi][0] = AsL[tg*SW + rb];
            afH[mi][1] = AsH[tg*SW + rb+8];     afL[mi][1] = AsL[tg*SW + rb+8];
            afH[mi][2] = AsH[(tg+4)*SW + rb];   afL[mi][2] = AsL[(tg+4)*SW + rb];
            afH[mi][3] = AsH[(tg+4)*SW + rb+8]; afL[mi][3] = AsL[(tg+4)*SW + rb+8];
        }
        #pragma unroll
        for (int ni = 0; ni < 4; ni++) {
            int cb = wn*32 + ni*8 + g;
            unsigned bH0 = BsH[tg*SWB + cb], bH1 = BsH[(tg+4)*SWB + cb];
            unsigned bL0 = BsL[tg*SWB + cb], bL1 = BsL[(tg+4)*SWB + cb];
            #pragma unroll
            for (int mi = 0; mi < 2; mi++) {
                mma_bf16(acc[mi][ni][0], acc[mi][ni][1], acc[mi][ni][2], acc[mi][ni][3],
                         afH[mi][0], afH[mi][1], afH[mi][2], afH[mi][3], bL0, bL1);
                mma_bf16(acc[mi][ni][0], acc[mi][ni][1], acc[mi][ni][2], acc[mi][ni][3],
                         afL[mi][0], afL[mi][1], afL[mi][2], afL[mi][3], bH0, bH1);
                mma_bf16(acc[mi][ni][0], acc[mi][ni][1], acc[mi][ni][2], acc[mi][ni][3],
                         afH[mi][0], afH[mi][1], afH[mi][2], afH[mi][3], bH0, bH1);
            }
        }
        __syncthreads();
    }

    #pragma unroll
    for (int mi = 0; mi < 2; mi++) {
        #pragma unroll
        for (int ni = 0; ni < 4; ni++) {
            int row = by*128 + wm*32 + mi*16 + g;
            int col = wn*32 + ni*8 + tg*2;
            float* o0 = O + (size_t)(b*SEQ + row)*DIM + h*DHEAD + col;
            float* o1 = O + (size_t)(b*SEQ + row + 8)*DIM + h*DHEAD + col;
            float v0 = acc[mi][ni][0], v1 = acc[mi][ni][1];
            float v2 = acc[mi][ni][2], v3 = acc[mi][ni][3];
            if (accum) {
                float2 r0 = *reinterpret_cast<const float2*>(o0);
                float2 r1 = *reinterpret_cast<const float2*>(o1);
                v0 += r0.x; v1 += r0.y; v2 += r1.x; v3 += r1.y;
            }
            *reinterpret_cast<float2*>(o0) = make_float2(v0, v1);
            *reinterpret_cast<float2*>(o1) = make_float2(v2, v3);
        }
    }
}

// -------- top-32 per (bh,i) -------------------------------------------------
__global__ __launch_bounds__(256)
void topk_kernel(const float* __restrict__ S, float* __restrict__ TV,
                 int* __restrict__ TI) {
    int i = blockIdx.x, bh = blockIdx.y;
    const float* row = S + ((size_t)bh*SEQ + i)*MEMN;
    __shared__ float sv[MEMN];
    __shared__ float wv[8];
    __shared__ int   wi[8];
    __shared__ int wini;
    int tid = threadIdx.x;

    float lmax = -1e30f; int lidx = 0;
    #pragma unroll 4
    for (int j = 0; j < 16; j++) {
        int m = tid + 256*j;
        float v = row[m];
        sv[m] = v;
        if (v > lmax) { lmax = v; lidx = m; }
    }
    for (int t = 0; t < TOPK; t++) {
        float v = lmax; int idx = lidx;
        #pragma unroll
        for (int o = 16; o > 0; o >>= 1) {
            float ov = __shfl_xor_sync(0xffffffffu, v, o);
            int   oi = __shfl_xor_sync(0xffffffffu, idx, o);
            if (ov > v) { v = ov; idx = oi; }
        }
        if ((tid & 31) == 0) { wv[tid>>5] = v; wi[tid>>5] = idx; }
        __syncthreads();
        if (tid < 32) {
            float v2 = (tid < 8) ? wv[tid] : -1e30f;
            int   i2 = (tid < 8) ? wi[tid] : 0;
            #pragma unroll
            for (int o = 4; o > 0; o >>= 1) {
                float ov = __shfl_xor_sync(0xffffffffu, v2, o);
                int   oi = __shfl_xor_sync(0xffffffffu, i2, o);
                if (ov > v2) { v2 = ov; i2 = oi; }
            }
            if (tid == 0) {
                wini = i2;
                TV[((size_t)bh*SEQ + i)*TOPK + t] = v2;
                TI[((size_t)bh*SEQ + i)*TOPK + t] = i2;
            }
        }
        __syncthreads();
        int widx = wini;
        if ((widx & 255) == tid) {
            sv[widx] = -1e30f;
            lmax = -1e30f; lidx = 0;
            #pragma unroll 4
            for (int j = 0; j < 16; j++) {
                int m = tid + 256*j;
                float vv = sv[m];
                if (vv > lmax) { lmax = vv; lidx = m; }
            }
        }
    }
}

// ---------------- host orchestration --------------------------------------
extern "C" void kernel_launch(void* const* d_in, const int* in_sizes, int n_in,
                              void* d_out, int out_size) {
    const float* x     = (const float*)d_in[0];
    const float* Wq    = (const float*)d_in[1];
    const float* Wk    = (const float*)d_in[2];
    const float* Wv    = (const float*)d_in[3];
    const float* Wo    = (const float*)d_in[4];
    const float* ln1s  = (const float*)d_in[5];
    const float* ln1b  = (const float*)d_in[6];
    const float* ln2s  = (const float*)d_in[7];
    const float* ln2b  = (const float*)d_in[8];
    const float* W1    = (const float*)d_in[9];
    const float* W2    = (const float*)d_in[10];
    const float* lnfs  = (const float*)d_in[11];
    const float* lnfb  = (const float*)d_in[12];
    const float* mem_k = (const float*)d_in[13];
    const float* mem_v = (const float*)d_in[14];

    float *X, *H, *Q, *K, *V, *AO, *FFb, *S, *P, *TV;
    int *TI; unsigned *WH, *WL;
    cudaGetSymbolAddress((void**)&X,  g_X);
    cudaGetSymbolAddress((void**)&H,  g_H);
    cudaGetSymbolAddress((void**)&Q,  g_Q);
    cudaGetSymbolAddress((void**)&K,  g_K);
    cudaGetSymbolAddress((void**)&V,  g_V);
    cudaGetSymbolAddress((void**)&AO, g_AO);
    cudaGetSymbolAddress((void**)&FFb, g_FF);
    cudaGetSymbolAddress((void**)&S,  g_S);
    cudaGetSymbolAddress((void**)&P,  g_P);
    cudaGetSymbolAddress((void**)&TV, g_TV);
    cudaGetSymbolAddress((void**)&TI, g_TI);
    cudaGetSymbolAddress((void**)&WH, g_WH);
    cudaGetSymbolAddress((void**)&WL, g_WL);

    cudaMemcpyAsync(X, x, sizeof(float) * MROWS * DIM, cudaMemcpyDeviceToDevice);

    // weight pre-split (runs inside the graph; memory-bound, ~25us total)
    const int OQ = 0, OK = 6*PQ, OV = 12*PQ, OO = 18*PQ, O1 = 24*PQ, O2 = 24*PQ + 6*PF;
    split_w<<<dim3(PQ/256, DEPTH), 256>>>(Wq, WH + OQ, WL + OQ, PQ, DIM);
    split_w<<<dim3(PQ/256, DEPTH), 256>>>(Wk, WH + OK, WL + OK, PQ, DIM);
    split_w<<<dim3(PQ/256, DEPTH), 256>>>(Wv, WH + OV, WL + OV, PQ, DIM);
    split_w<<<dim3(PQ/256, DEPTH), 256>>>(Wo, WH + OO, WL + OO, PQ, DIM);
    split_w<<<dim3(PF/256, DEPTH), 256>>>(W1, WH + O1, WL + O1, PF, FFDIM);
    split_w<<<dim3(PF/256, DEPTH), 256>>>(W2, WH + O2, WL + O2, PF, DIM);

    dim3 gD(DIM/128, MROWS/128);
    dim3 gQKV(DIM/128, MROWS/128, 3);
    dim3 gF(FFDIM/128, MROWS/128);
    dim3 gSim(MEMN/128, SEQ/128, NBH);
    dim3 gLoc(SEQ/128, SEQ/128, NBH);
    dim3 gRow(SEQ, NBH);
    dim3 gAV(MROWS/128 / BATCH, NBH);

    int mi = 0;
    for (int l = 0; l < DEPTH; l++) {
        ln_kernel<<<MROWS, 128>>>(X, ln1s + l*DIM, ln1b + l*DIM, H);
        gemm_qkv<<<gQKV, 256>>>(H, WH, WL, OQ + l*PQ, OK + l*PQ, OV + l*PQ, Q, K, V);
        if (l == 3 || l == 4) {
            const float* MK = mem_k + (size_t)mi * BATCH * MEMN * DHEAD;
            const float* MV = mem_v + (size_t)mi * BATCH * MEMN * DHEAD;
            knn_sim_tc<<<gSim, 256>>>(Q, MK, S);
            topk_kernel<<<gRow, 256>>>(S, TV, TI);
            sim_local_tc<<<gLoc, 256>>>(Q, K, P);
            softmax_knn<<<gRow, 128>>>(P, TV);
            mem_gather<<<gRow, 64>>>(MV, TV, TI, AO);
            av_tc<<<gAV, 256>>>(P, V, AO, 1);
            mi++;
        } else {
            sim_local_tc<<<gLoc, 256>>>(Q, K, P);
            softmax_causal<<<gRow, 128>>>(P);
            av_tc<<<gAV, 256>>>(P, V, AO, 0);
        }
        gemm_tc<<<gD, 256>>>(AO, WH + OO + l*PQ, WL + OO + l*PQ, X, X, DIM, DIM, 0);
        ln_kernel<<<MROWS, 128>>>(X, ln2s + l*DIM, ln2b + l*DIM, H);
        gemm_tc<<<gF, 256>>>(H, WH + O1 + l*PF, WL + O1 + l*PF, nullptr, FFb, FFDIM, DIM, 1);
        gemm_tc<<<gD, 256>>>(FFb, WH + O2 + l*PF, WL + O2 + l*PF, X, X, DIM, FFDIM, 0);
    }
    ln_kernel<<<MROWS, 128>>>(X, lnfs, lnfb, (float*)d_out);
}